// round 8
// baseline (speedup 1.0000x reference)
#include <cuda_runtime.h>
#include <cuda_fp16.h>
#include <cstdint>

// Problem constants: B=8, D=8, H=W=56, C=128, 4 heads x 32, windows (8,7,7),
// all pads zero. xy: 4096 windows x 49 tok; th/tw: 3584 x 56.
//
// fp16 storage, fp32 accumulate, mma.m16n8k16.
// QKV: kt-outer, A-fragments loaded ONCE and reused for q+k (pass 1) and v
// (pass 2); B-fragments straight from pre-transposed fp16 weights in global
// (L1-resident) -> no QKV smem staging at all.
// X/Q/K: pair-permuted column layout (pos 4i..4i+3 = cols 2i,2i+1,2i+8,2i+9).
// V plain row-major; PV B-frags via ldmatrix.x4.trans.
// P register-resident (scores C-frag == PV A-frag). th/tw accumulate via REDG.

static constexpr int SH   = 144;  // stride (halves) for X/Q/K rows
static constexpr int WSH  = 144;  // stride for staged proj weight rows
static constexpr int VS   = 136;  // stride for V rows (272B -> conflict-free LDSM)

static constexpr int OFF_X  = 0;                    // 64 x SH (x, later attn out)
static constexpr int OFF_Q  = OFF_X + 64 * SH;
static constexpr int OFF_K  = OFF_Q + 64 * SH;
static constexpr int OFF_V  = OFF_K + 64 * SH;      // 64 x VS, plain layout
static constexpr int OFF_W  = OFF_V + 64 * VS;      // 128 x WSH staged proj weights
static constexpr int TOT_HALVES = OFF_W + 128 * WSH;           // 54784
static constexpr int SMEM_BYTES = TOT_HALVES * 2 + 64 * 4;     // 109824 -> 2 CTAs/SM

// Pre-converted fp16 weights, transposed (row = output col n, col = k perm).
__device__ __align__(16) __half g_qkvwt[3][384 * 128];
__device__ __align__(16) __half g_projwt[3][128 * 128];

template <int BRANCH>
__device__ __forceinline__ int tok_index(int win, int tt) {
    if (BRANCH == 0) {                 // xy: (b, d, hb, wb) x (hh, ww)
        int b  = win >> 9;
        int d  = (win >> 6) & 7;
        int hb = (win >> 3) & 7;
        int wb = win & 7;
        int hh = tt / 7, wq = tt - hh * 7;
        return ((b * 8 + d) * 56 + hb * 7 + hh) * 56 + wb * 7 + wq;
    } else if (BRANCH == 1) {          // th: (b, hb, w) x (dd, hh)
        int b  = win / 448;
        int r  = win - b * 448;
        int hb = r / 56;
        int w  = r - hb * 56;
        int dd = tt / 7, hh = tt - dd * 7;
        return ((b * 8 + dd) * 56 + hb * 7 + hh) * 56 + w;
    } else {                           // tw: (b, h, wb) x (dd, ww)
        int b  = win / 448;
        int r  = win - b * 448;
        int h  = r >> 3;
        int wb = r & 7;
        int dd = tt / 7, wq = tt - dd * 7;
        return ((b * 8 + dd) * 56 + h) * 56 + wb * 7 + wq;
    }
}

// D += A(16x16) * B(16x8), f16 in, f32 accumulate.
__device__ __forceinline__ void mma16(float4& d, uint32_t a0, uint32_t a1,
                                      uint32_t a2, uint32_t a3,
                                      uint32_t b0, uint32_t b1) {
    asm volatile(
        "mma.sync.aligned.m16n8k16.row.col.f32.f16.f16.f32 "
        "{%0,%1,%2,%3}, {%4,%5,%6,%7}, {%8,%9}, {%0,%1,%2,%3};\n"
        : "+f"(d.x), "+f"(d.y), "+f"(d.z), "+f"(d.w)
        : "r"(a0), "r"(a1), "r"(a2), "r"(a3), "r"(b0), "r"(b1));
}

// ldmatrix x4 with in-flight transpose (b16 elements).
__device__ __forceinline__ void ldsm_x4_t(uint32_t& r0, uint32_t& r1,
                                          uint32_t& r2, uint32_t& r3,
                                          uint32_t addr) {
    asm volatile("ldmatrix.sync.aligned.m8n8.x4.trans.shared.b16 "
                 "{%0,%1,%2,%3}, [%4];"
                 : "=r"(r0), "=r"(r1), "=r"(r2), "=r"(r3) : "r"(addr));
}

__device__ __forceinline__ uint32_t h2u(float a, float b) {
    __half2 h = __floats2half2_rn(a, b);
    return *(uint32_t*)&h;
}

// ---------------- weight pre-conversion (runs once per launch) ----------------
__global__ void conv_weights(const float* __restrict__ w0, const float* __restrict__ w1,
                             const float* __restrict__ w2, const float* __restrict__ p0,
                             const float* __restrict__ p1, const float* __restrict__ p2) {
    int tid = blockIdx.x * 256 + threadIdx.x;
    const int QK = 3 * 384 * 128;
    if (tid < QK) {
        int br  = tid / (384 * 128);
        int rem = tid - br * 384 * 128;
        int n = rem >> 7, kp = rem & 127;
        int b = kp >> 4, p = kp & 15;
        int k = b * 16 + ((p >> 2) * 2) + (p & 1) + ((p & 2) ? 8 : 0);
        const float* src = (br == 0) ? w0 : (br == 1 ? w1 : w2);
        g_qkvwt[br][rem] = __float2half_rn(src[k * 384 + n]);
    } else {
        int t2  = tid - QK;
        int br  = t2 / (128 * 128);
        int rem = t2 - br * 16384;
        int n = rem >> 7, kp = rem & 127;
        int b = kp >> 4, p = kp & 15;
        int k = b * 16 + ((p >> 2) * 2) + (p & 1) + ((p & 2) ? 8 : 0);
        const float* src = (br == 0) ? p0 : (br == 1 ? p1 : p2);
        g_projwt[br][rem] = __float2half_rn(src[k * 128 + n]);
    }
}

// ---------------- fused window attention, one CTA per window ----------------
template <int BRANCH, int NTOK>
__global__ void __launch_bounds__(512, 2)
win_attn_h(const float* __restrict__ x,
           const float* __restrict__ qkvb, const float* __restrict__ projb,
           float* __restrict__ out)
{
    extern __shared__ __align__(16) __half smh[];
    int* tokidx = (int*)(smh + TOT_HALVES);
    const uint32_t smem_u32 = (uint32_t)__cvta_generic_to_shared(smh);

    const int t    = threadIdx.x;
    const int lane = t & 31;
    const int wrp  = t >> 5;        // 0..15
    const int g    = lane >> 2;
    const int tg   = lane & 3;
    const int win  = blockIdx.x;

    if (t < NTOK) tokidx[t] = tok_index<BRANCH>(win, t);

    // ---- x -> X (fp16, permuted), pad rows zeroed. 32 uint2 chunks/row ----
    for (int idx = t; idx < 64 * 32; idx += 512) {
        int r = idx >> 5, q = idx & 31;
        int b = q >> 2, i = q & 3;
        uint2 u = make_uint2(0u, 0u);
        if (r < NTOK) {
            const float* row = x + (size_t)tok_index<BRANCH>(win, r) * 128 + b * 16 + 2 * i;
            float2 lo = *(const float2*)row;        // cols 2i, 2i+1
            float2 hi = *(const float2*)(row + 8);  // cols 2i+8, 2i+9
            u.x = h2u(lo.x, lo.y);
            u.y = h2u(hi.x, hi.y);
        }
        *(uint2*)&smh[OFF_X + r * SH + q * 4] = u;
    }
    __syncthreads();

    const int mb = (wrp & 1) * 2;        // m-tiles {mb, mb+1}
    const int n0 = (wrp >> 1) * 16;      // n columns [n0, n0+16)
    const float qscale = 0.1767766952966369f;

    // ---- QKV pass 1: q and k chunks together, kt-outer (A loaded once) ----
    {
        const __half* wq = g_qkvwt[BRANCH];
        const __half* wk = g_qkvwt[BRANCH] + 128 * 128;

        float4 acc[2][2][2];    // [chunk q/k][m][n]
        #pragma unroll
        for (int c = 0; c < 2; c++)
            #pragma unroll
            for (int n = 0; n < 2; n++) {
                float b0 = qkvb[c * 128 + n0 + n * 8 + 2 * tg];
                float b1 = qkvb[c * 128 + n0 + n * 8 + 2 * tg + 1];
                acc[c][0][n] = make_float4(b0, b1, b0, b1);
                acc[c][1][n] = acc[c][0][n];
            }

        #pragma unroll 4
        for (int kt = 0; kt < 8; kt++) {
            int kb = kt * 16;
            uint2 A[2][2];
            #pragma unroll
            for (int m = 0; m < 2; m++) {
                int r = (mb + m) * 16 + g;
                A[m][0] = *(const uint2*)&smh[OFF_X + r * SH + kb + 4 * tg];
                A[m][1] = *(const uint2*)&smh[OFF_X + (r + 8) * SH + kb + 4 * tg];
            }
            #pragma unroll
            for (int c = 0; c < 2; c++) {
                const __half* ws = c ? wk : wq;
                uint2 B[2];
                #pragma unroll
                for (int n = 0; n < 2; n++) {
                    int nn = n0 + n * 8 + g;
                    B[n] = *(const uint2*)&ws[nn * 128 + kb + 4 * tg];
                }
                #pragma unroll
                for (int m = 0; m < 2; m++)
                    #pragma unroll
                    for (int n = 0; n < 2; n++)
                        mma16(acc[c][m][n], A[m][0].x, A[m][1].x, A[m][0].y,
                              A[m][1].y, B[n].x, B[n].y);
            }
        }

        // store q (scaled) and k: activation layout, permuted half2 stores
        #pragma unroll
        for (int c = 0; c < 2; c++) {
            const int dst = (c == 0) ? OFF_Q : OFF_K;
            const float mul = (c == 0) ? qscale : 1.0f;
            #pragma unroll
            for (int m = 0; m < 2; m++) {
                int r = (mb + m) * 16 + g;
                #pragma unroll
                for (int n = 0; n < 2; n++) {
                    int pos = n0 + 4 * tg + 2 * n;   // perm of col n0+n*8+2tg
                    *(uint32_t*)&smh[dst + r * SH + pos] =
                        h2u(acc[c][m][n].x * mul, acc[c][m][n].y * mul);
                    *(uint32_t*)&smh[dst + (r + 8) * SH + pos] =
                        h2u(acc[c][m][n].z * mul, acc[c][m][n].w * mul);
                }
            }
        }
    }

    // ---- QKV pass 2: v chunk (A reloaded once more) ----
    {
        const __half* wv = g_qkvwt[BRANCH] + 2 * 128 * 128;
        float4 acc[2][2];
        #pragma unroll
        for (int n = 0; n < 2; n++) {
            float b0 = qkvb[256 + n0 + n * 8 + 2 * tg];
            float b1 = qkvb[256 + n0 + n * 8 + 2 * tg + 1];
            acc[0][n] = make_float4(b0, b1, b0, b1);
            acc[1][n] = acc[0][n];
        }
        #pragma unroll 4
        for (int kt = 0; kt < 8; kt++) {
            int kb = kt * 16;
            uint2 A[2][2];
            #pragma unroll
            for (int m = 0; m < 2; m++) {
                int r = (mb + m) * 16 + g;
                A[m][0] = *(const uint2*)&smh[OFF_X + r * SH + kb + 4 * tg];
                A[m][1] = *(const uint2*)&smh[OFF_X + (r + 8) * SH + kb + 4 * tg];
            }
            uint2 B[2];
            #pragma unroll
            for (int n = 0; n < 2; n++) {
                int nn = n0 + n * 8 + g;
                B[n] = *(const uint2*)&wv[nn * 128 + kb + 4 * tg];
            }
            #pragma unroll
            for (int m = 0; m < 2; m++)
                #pragma unroll
                for (int n = 0; n < 2; n++)
                    mma16(acc[m][n], A[m][0].x, A[m][1].x, A[m][0].y, A[m][1].y,
                          B[n].x, B[n].y);
        }
        // v: plain row-major [token][channel], vector stores
        #pragma unroll
        for (int m = 0; m < 2; m++) {
            int r = (mb + m) * 16 + g;
            #pragma unroll
            for (int n = 0; n < 2; n++) {
                int c = n0 + n * 8 + 2 * tg;
                *(uint32_t*)&smh[OFF_V + r * VS + c]       = h2u(acc[m][n].x, acc[m][n].y);
                *(uint32_t*)&smh[OFF_V + (r + 8) * VS + c] = h2u(acc[m][n].z, acc[m][n].w);
            }
        }
    }

    // Prefetch proj weights into OFF_W (overlaps with scores/attn compute).
    {
        const __half* psrc = g_projwt[BRANCH];
        for (int idx = t; idx < 128 * 16; idx += 512) {
            int rw = idx >> 4, c8 = idx & 15;
            *(uint4*)&smh[OFF_W + rw * WSH + c8 * 8] = *(const uint4*)&psrc[rw * 128 + c8 * 8];
        }
    }
    __syncthreads();   // Q, K, V complete (proj staging covered by next barrier)

    // ---- scores + softmax + P@V, P fully register-resident ----
    const int h  = wrp >> 2;
    const int mt = wrp & 3;
    const int r0 = mt * 16 + g;
    {
        float4 sacc[7];
        #pragma unroll
        for (int n = 0; n < 7; n++) sacc[n] = make_float4(0.f, 0.f, 0.f, 0.f);
        #pragma unroll
        for (int kt = 0; kt < 2; kt++) {
            int kb = h * 32 + kt * 16;
            uint2 A0 = *(const uint2*)&smh[OFF_Q + r0 * SH + kb + 4 * tg];
            uint2 A1 = *(const uint2*)&smh[OFF_Q + (r0 + 8) * SH + kb + 4 * tg];
            #pragma unroll
            for (int n = 0; n < 7; n++) {
                uint2 Bn = *(const uint2*)&smh[OFF_K + (n * 8 + g) * SH + kb + 4 * tg];
                mma16(sacc[n], A0.x, A1.x, A0.y, A1.y, Bn.x, Bn.y);
            }
        }

        // register softmax; rows r0 (x,y) and r0+8 (z,w) live in this lane quad
        if (NTOK < 56) {
            #pragma unroll
            for (int n = 0; n < 7; n++) {
                int j0 = 8 * n + 2 * tg;
                if (j0 >= NTOK)     { sacc[n].x = -1e30f; sacc[n].z = -1e30f; }
                if (j0 + 1 >= NTOK) { sacc[n].y = -1e30f; sacc[n].w = -1e30f; }
            }
        }
        float mA = -1e30f, mB = -1e30f;
        #pragma unroll
        for (int n = 0; n < 7; n++) {
            mA = fmaxf(mA, fmaxf(sacc[n].x, sacc[n].y));
            mB = fmaxf(mB, fmaxf(sacc[n].z, sacc[n].w));
        }
        #pragma unroll
        for (int o = 1; o <= 2; o <<= 1) {
            mA = fmaxf(mA, __shfl_xor_sync(~0u, mA, o));
            mB = fmaxf(mB, __shfl_xor_sync(~0u, mB, o));
        }
        float sA = 0.f, sB = 0.f;
        #pragma unroll
        for (int n = 0; n < 7; n++) {
            sacc[n].x = __expf(sacc[n].x - mA);
            sacc[n].y = __expf(sacc[n].y - mA);
            sacc[n].z = __expf(sacc[n].z - mB);
            sacc[n].w = __expf(sacc[n].w - mB);
            sA += sacc[n].x + sacc[n].y;
            sB += sacc[n].z + sacc[n].w;
        }
        #pragma unroll
        for (int o = 1; o <= 2; o <<= 1) {
            sA += __shfl_xor_sync(~0u, sA, o);
            sB += __shfl_xor_sync(~0u, sB, o);
        }
        float iA = 1.0f / sA, iB = 1.0f / sB;

        // Pack P into PV A-fragment registers (scores C-frag == A-frag layout).
        uint32_t pA[7], pB[7];
        #pragma unroll
        for (int n = 0; n < 7; n++) {
            pA[n] = h2u(sacc[n].x * iA, sacc[n].y * iA);
            pB[n] = h2u(sacc[n].z * iB, sacc[n].w * iB);
        }

        // ---- attn @ V: B-frags via ldmatrix.trans on plain-layout V ----
        const int li  = lane & 7;
        const int grp = lane >> 3;
        float4 vacc[4];
        #pragma unroll
        for (int n = 0; n < 4; n++) vacc[n] = make_float4(0.f, 0.f, 0.f, 0.f);
        #pragma unroll
        for (int kt = 0; kt < 4; kt++) {
            int kb = kt * 16;
            int vrow = kb + ((grp & 1) << 3) + li;
            int vcol = h * 32 + ((grp >> 1) << 3);
            uint32_t addr = smem_u32 + (uint32_t)(OFF_V + vrow * VS + vcol) * 2;
            uint32_t b00, b01, b10, b11;   // channels [h*32, h*32+16)
            ldsm_x4_t(b00, b01, b10, b11, addr);
            uint32_t b20, b21, b30, b31;   // channels [h*32+16, h*32+32)
            ldsm_x4_t(b20, b21, b30, b31, addr + 32);

            uint32_t a0 = pA[2 * kt], a1 = pB[2 * kt];
            uint32_t a2 = (2 * kt + 1 < 7) ? pA[2 * kt + 1] : 0u;  // j pad = 0
            uint32_t a3 = (2 * kt + 1 < 7) ? pB[2 * kt + 1] : 0u;
            mma16(vacc[0], a0, a1, a2, a3, b00, b01);
            mma16(vacc[1], a0, a1, a2, a3, b10, b11);
            mma16(vacc[2], a0, a1, a2, a3, b20, b21);
            mma16(vacc[3], a0, a1, a2, a3, b30, b31);
        }
        #pragma unroll
        for (int n = 0; n < 4; n++) {
            int pos = h * 32 + (n >> 1) * 16 + 4 * tg + 2 * (n & 1);
            *(uint32_t*)&smh[OFF_X + r0 * SH + pos]       = h2u(vacc[n].x, vacc[n].y);
            *(uint32_t*)&smh[OFF_X + (r0 + 8) * SH + pos] = h2u(vacc[n].z, vacc[n].w);
        }
    }
    __syncthreads();   // attn output complete; proj weights staged

    // ---- proj GEMM: attnout(64x128) @ Wproj(128x128) -> global ----
    {
        float4 acc[2][2];
        #pragma unroll
        for (int n = 0; n < 2; n++) {
            float b0 = projb[n0 + n * 8 + 2 * tg];
            float b1 = projb[n0 + n * 8 + 2 * tg + 1];
            acc[0][n] = make_float4(b0, b1, b0, b1);
            acc[1][n] = acc[0][n];
        }
        #pragma unroll 4
        for (int kt = 0; kt < 8; kt++) {
            int kb = kt * 16;
            uint2 A[2][2];
            #pragma unroll
            for (int m = 0; m < 2; m++) {
                int r = (mb + m) * 16 + g;
                A[m][0] = *(const uint2*)&smh[OFF_X + r * SH + kb + 4 * tg];
                A[m][1] = *(const uint2*)&smh[OFF_X + (r + 8) * SH + kb + 4 * tg];
            }
            uint2 B[2];
            #pragma unroll
            for (int n = 0; n < 2; n++) {
                int nn = n0 + n * 8 + g;
                B[n] = *(const uint2*)&smh[OFF_W + nn * WSH + kb + 4 * tg];
            }
            #pragma unroll
            for (int m = 0; m < 2; m++)
                #pragma unroll
                for (int n = 0; n < 2; n++)
                    mma16(acc[m][n], A[m][0].x, A[m][1].x, A[m][0].y, A[m][1].y,
                          B[n].x, B[n].y);
        }

        #pragma unroll
        for (int m = 0; m < 2; m++) {
            #pragma unroll
            for (int rr = 0; rr < 2; rr++) {
                int r = (mb + m) * 16 + g + rr * 8;
                if (r < NTOK) {
                    #pragma unroll
                    for (int n = 0; n < 2; n++) {
                        float2 val = rr ? make_float2(acc[m][n].z, acc[m][n].w)
                                        : make_float2(acc[m][n].x, acc[m][n].y);
                        size_t o = (size_t)tokidx[r] * 128 + n0 + n * 8 + 2 * tg;
                        if (BRANCH == 0) {
                            *(float2*)&out[o] = val;
                        } else {
                            asm volatile("red.global.add.v2.f32 [%0], {%1, %2};"
                                         :: "l"(out + o), "f"(val.x), "f"(val.y)
                                         : "memory");
                        }
                    }
                }
            }
        }
    }
}

extern "C" void kernel_launch(void* const* d_in, const int* in_sizes, int n_in,
                              void* d_out, int out_size)
{
    const float* x         = (const float*)d_in[0];
    const float* qkv_w     = (const float*)d_in[1];
    const float* qkv_b     = (const float*)d_in[2];
    const float* qkv_th_w  = (const float*)d_in[3];
    const float* qkv_th_b  = (const float*)d_in[4];
    const float* qkv_tw_w  = (const float*)d_in[5];
    const float* qkv_tw_b  = (const float*)d_in[6];
    const float* proj_w    = (const float*)d_in[7];
    const float* proj_b    = (const float*)d_in[8];
    const float* proj_th_w = (const float*)d_in[9];
    const float* proj_th_b = (const float*)d_in[10];
    const float* proj_tw_w = (const float*)d_in[11];
    const float* proj_tw_b = (const float*)d_in[12];
    float* out = (float*)d_out;

    conv_weights<<<768, 256>>>(qkv_w, qkv_th_w, qkv_tw_w,
                               proj_w, proj_th_w, proj_tw_w);

    cudaFuncSetAttribute(win_attn_h<0, 49>,
                         cudaFuncAttributeMaxDynamicSharedMemorySize, SMEM_BYTES);
    cudaFuncSetAttribute(win_attn_h<1, 56>,
                         cudaFuncAttributeMaxDynamicSharedMemorySize, SMEM_BYTES);
    cudaFuncSetAttribute(win_attn_h<2, 56>,
                         cudaFuncAttributeMaxDynamicSharedMemorySize, SMEM_BYTES);

    // xy writes every output exactly once; th / tw accumulate via REDG.
    win_attn_h<0, 49><<<4096, 512, SMEM_BYTES>>>(x, qkv_b, proj_b, out);
    win_attn_h<1, 56><<<3584, 512, SMEM_BYTES>>>(x, qkv_th_b, proj_th_b, out);
    win_attn_h<2, 56><<<3584, 512, SMEM_BYTES>>>(x, qkv_tw_b, proj_tw_b, out);
}

// round 10
// speedup vs baseline: 1.0282x; 1.0282x over previous
#include <cuda_runtime.h>
#include <cuda_fp16.h>
#include <cstdint>

// Problem constants: B=8, D=8, H=W=56, C=128, 4 heads x 32, windows (8,7,7),
// all pads zero. xy: 4096 windows x 49 tok; th/tw: 3584 x 56.
//
// 2 windows per CTA (1024 thr): warps 0-15 -> window A, 16-31 -> window B,
// sharing one staged weight buffer (staging bytes + barriers per window
// halved). Staging via cp.async.cg (no RF round trip).
// fp16 storage, fp32 accumulate, mma.m16n8k16. X/Q/K pair-permuted layout;
// V plain row-major with ldmatrix.x4.trans B-frags; P register-resident;
// th/tw accumulate via REDG.

static constexpr int SH   = 144;  // stride (halves) for X/Q/K rows
static constexpr int WSH  = 144;  // stride for staged weight rows
static constexpr int VS   = 136;  // stride for V rows

// Per-window activation block (halves)
static constexpr int OFF_X  = 0;                    // 64 x SH (x, later attn out)
static constexpr int OFF_Q  = OFF_X + 64 * SH;
static constexpr int OFF_K  = OFF_Q + 64 * SH;
static constexpr int OFF_V  = OFF_K + 64 * SH;      // 64 x VS
static constexpr int ACT_HALVES = OFF_V + 64 * VS;  // 36352
static constexpr int OFF_W  = 2 * ACT_HALVES;       // shared staged weights 128 x WSH
static constexpr int TOT_HALVES = OFF_W + 128 * WSH;           // 91136
static constexpr int SMEM_BYTES = TOT_HALVES * 2 + 128 * 4;    // 182784 (1 CTA/SM)

// Pre-converted fp16 weights, transposed (row = output col n, col = k perm).
__device__ __align__(16) __half g_qkvwt[3][384 * 128];
__device__ __align__(16) __half g_projwt[3][128 * 128];

template <int BRANCH>
__device__ __forceinline__ int tok_index(int win, int tt) {
    if (BRANCH == 0) {                 // xy: (b, d, hb, wb) x (hh, ww)
        int b  = win >> 9;
        int d  = (win >> 6) & 7;
        int hb = (win >> 3) & 7;
        int wb = win & 7;
        int hh = tt / 7, wq = tt - hh * 7;
        return ((b * 8 + d) * 56 + hb * 7 + hh) * 56 + wb * 7 + wq;
    } else if (BRANCH == 1) {          // th: (b, hb, w) x (dd, hh)
        int b  = win / 448;
        int r  = win - b * 448;
        int hb = r / 56;
        int w  = r - hb * 56;
        int dd = tt / 7, hh = tt - dd * 7;
        return ((b * 8 + dd) * 56 + hb * 7 + hh) * 56 + w;
    } else {                           // tw: (b, h, wb) x (dd, ww)
        int b  = win / 448;
        int r  = win - b * 448;
        int h  = r >> 3;
        int wb = r & 7;
        int dd = tt / 7, wq = tt - dd * 7;
        return ((b * 8 + dd) * 56 + h) * 56 + wb * 7 + wq;
    }
}

// D += A(16x16) * B(16x8), f16 in, f32 accumulate.
__device__ __forceinline__ void mma16(float4& d, uint32_t a0, uint32_t a1,
                                      uint32_t a2, uint32_t a3,
                                      uint32_t b0, uint32_t b1) {
    asm volatile(
        "mma.sync.aligned.m16n8k16.row.col.f32.f16.f16.f32 "
        "{%0,%1,%2,%3}, {%4,%5,%6,%7}, {%8,%9}, {%0,%1,%2,%3};\n"
        : "+f"(d.x), "+f"(d.y), "+f"(d.z), "+f"(d.w)
        : "r"(a0), "r"(a1), "r"(a2), "r"(a3), "r"(b0), "r"(b1));
}

// ldmatrix x4 with in-flight transpose (b16 elements).
__device__ __forceinline__ void ldsm_x4_t(uint32_t& r0, uint32_t& r1,
                                          uint32_t& r2, uint32_t& r3,
                                          uint32_t addr) {
    asm volatile("ldmatrix.sync.aligned.m8n8.x4.trans.shared.b16 "
                 "{%0,%1,%2,%3}, [%4];"
                 : "=r"(r0), "=r"(r1), "=r"(r2), "=r"(r3) : "r"(addr));
}

__device__ __forceinline__ void cp16(uint32_t dst, const void* src) {
    asm volatile("cp.async.cg.shared.global [%0], [%1], 16;"
                 :: "r"(dst), "l"(src));
}
__device__ __forceinline__ void cp_wait_all() {
    asm volatile("cp.async.commit_group;\n\tcp.async.wait_group 0;" ::: "memory");
}

__device__ __forceinline__ uint32_t h2u(float a, float b) {
    __half2 h = __floats2half2_rn(a, b);
    return *(uint32_t*)&h;
}

// ---------------- weight pre-conversion (runs once per launch) ----------------
__global__ void conv_weights(const float* __restrict__ w0, const float* __restrict__ w1,
                             const float* __restrict__ w2, const float* __restrict__ p0,
                             const float* __restrict__ p1, const float* __restrict__ p2) {
    int tid = blockIdx.x * 256 + threadIdx.x;
    const int QK = 3 * 384 * 128;
    if (tid < QK) {
        int br  = tid / (384 * 128);
        int rem = tid - br * 384 * 128;
        int n = rem >> 7, kp = rem & 127;
        int b = kp >> 4, p = kp & 15;
        int k = b * 16 + ((p >> 2) * 2) + (p & 1) + ((p & 2) ? 8 : 0);
        const float* src = (br == 0) ? w0 : (br == 1 ? w1 : w2);
        g_qkvwt[br][rem] = __float2half_rn(src[k * 384 + n]);
    } else {
        int t2  = tid - QK;
        int br  = t2 / (128 * 128);
        int rem = t2 - br * 16384;
        int n = rem >> 7, kp = rem & 127;
        int b = kp >> 4, p = kp & 15;
        int k = b * 16 + ((p >> 2) * 2) + (p & 1) + ((p & 2) ? 8 : 0);
        const float* src = (br == 0) ? p0 : (br == 1 ? p1 : p2);
        g_projwt[br][rem] = __float2half_rn(src[k * 128 + n]);
    }
}

// ------------- fused window attention, TWO windows per CTA -------------
template <int BRANCH, int NTOK>
__global__ void __launch_bounds__(1024, 1)
win_attn2(const float* __restrict__ x,
          const float* __restrict__ qkvb, const float* __restrict__ projb,
          float* __restrict__ out)
{
    extern __shared__ __align__(16) __half smh[];
    int* tokidx = (int*)(smh + TOT_HALVES);
    const uint32_t smem_u32 = (uint32_t)__cvta_generic_to_shared(smh);

    const int t    = threadIdx.x;          // 0..1023
    const int wh   = t >> 9;               // window half 0/1
    const int tl   = t & 511;              // local thread within half
    const int lane = t & 31;
    const int wrp  = tl >> 5;              // local warp 0..15
    const int g    = lane >> 2;
    const int tg   = lane & 3;
    const int win  = blockIdx.x * 2 + wh;
    const int base = wh * ACT_HALVES;      // activation block for this window

    if (tl < NTOK) tokidx[wh * 64 + tl] = tok_index<BRANCH>(win, tl);

    // ---- x -> X (fp16, permuted), pad rows zeroed. 32 uint2 chunks/row ----
    for (int idx = tl; idx < 64 * 32; idx += 512) {
        int r = idx >> 5, q = idx & 31;
        int b = q >> 2, i = q & 3;
        uint2 u = make_uint2(0u, 0u);
        if (r < NTOK) {
            const float* row = x + (size_t)tok_index<BRANCH>(win, r) * 128 + b * 16 + 2 * i;
            float2 lo = *(const float2*)row;        // cols 2i, 2i+1
            float2 hi = *(const float2*)(row + 8);  // cols 2i+8, 2i+9
            u.x = h2u(lo.x, lo.y);
            u.y = h2u(hi.x, hi.y);
        }
        *(uint2*)&smh[base + OFF_X + r * SH + q * 4] = u;
    }
    // (x visibility covered by the first staging barrier below)

    const int mb = (wrp & 1) * 2;        // m-tiles {mb, mb+1}
    const int n0 = (wrp >> 1) * 16;      // n columns [n0, n0+16)
    const float qscale = 0.1767766952966369f;

    // ---- QKV GEMM: X(64x128) @ W chunk(128x128), chunks q,k,v ----
    #pragma unroll 1
    for (int cc = 0; cc < 3; cc++) {
        const __half* wsrc = g_qkvwt[BRANCH] + cc * 128 * 128;
        for (int idx = t; idx < 128 * 16; idx += 1024) {   // whole CTA stages once
            int rw = idx >> 4, c8 = idx & 15;
            cp16(smem_u32 + (uint32_t)(OFF_W + rw * WSH + c8 * 8) * 2,
                 wsrc + rw * 128 + c8 * 8);
        }
        cp_wait_all();
        __syncthreads();

        float4 acc[2][2];
        #pragma unroll
        for (int n = 0; n < 2; n++) {
            float b0 = qkvb[cc * 128 + n0 + n * 8 + 2 * tg];
            float b1 = qkvb[cc * 128 + n0 + n * 8 + 2 * tg + 1];
            acc[0][n] = make_float4(b0, b1, b0, b1);
            acc[1][n] = acc[0][n];
        }

        #pragma unroll 4
        for (int kt = 0; kt < 8; kt++) {
            int kb = kt * 16;
            uint2 A[2][2];
            #pragma unroll
            for (int m = 0; m < 2; m++) {
                int r = (mb + m) * 16 + g;
                A[m][0] = *(const uint2*)&smh[base + OFF_X + r * SH + kb + 4 * tg];
                A[m][1] = *(const uint2*)&smh[base + OFF_X + (r + 8) * SH + kb + 4 * tg];
            }
            uint2 B[2];
            #pragma unroll
            for (int n = 0; n < 2; n++) {
                int nn = n0 + n * 8 + g;
                B[n] = *(const uint2*)&smh[OFF_W + nn * WSH + kb + 4 * tg];
            }
            #pragma unroll
            for (int m = 0; m < 2; m++)
                #pragma unroll
                for (int n = 0; n < 2; n++)
                    mma16(acc[m][n], A[m][0].x, A[m][1].x, A[m][0].y, A[m][1].y,
                          B[n].x, B[n].y);
        }

        if (cc < 2) {   // q or k: activation layout, permuted half2 stores
            const int dst = base + ((cc == 0) ? OFF_Q : OFF_K);
            const float mul = (cc == 0) ? qscale : 1.0f;
            #pragma unroll
            for (int m = 0; m < 2; m++) {
                int r = (mb + m) * 16 + g;
                #pragma unroll
                for (int n = 0; n < 2; n++) {
                    int pos = n0 + 4 * tg + 2 * n;   // perm of col n0+n*8+2tg
                    *(uint32_t*)&smh[dst + r * SH + pos] =
                        h2u(acc[m][n].x * mul, acc[m][n].y * mul);
                    *(uint32_t*)&smh[dst + (r + 8) * SH + pos] =
                        h2u(acc[m][n].z * mul, acc[m][n].w * mul);
                }
            }
        } else {        // v: plain row-major [token][channel], vector stores
            #pragma unroll
            for (int m = 0; m < 2; m++) {
                int r = (mb + m) * 16 + g;
                #pragma unroll
                for (int n = 0; n < 2; n++) {
                    int c = n0 + n * 8 + 2 * tg;
                    *(uint32_t*)&smh[base + OFF_V + r * VS + c] =
                        h2u(acc[m][n].x, acc[m][n].y);
                    *(uint32_t*)&smh[base + OFF_V + (r + 8) * VS + c] =
                        h2u(acc[m][n].z, acc[m][n].w);
                }
            }
        }
        __syncthreads();   // consumption of OFF_W done before restage
    }

    // Prefetch proj weights (cp.async overlaps with scores/attn compute).
    {
        const __half* psrc = g_projwt[BRANCH];
        for (int idx = t; idx < 128 * 16; idx += 1024) {
            int rw = idx >> 4, c8 = idx & 15;
            cp16(smem_u32 + (uint32_t)(OFF_W + rw * WSH + c8 * 8) * 2,
                 psrc + rw * 128 + c8 * 8);
        }
    }

    // ---- scores + softmax + P@V, P fully register-resident ----
    const int h  = wrp >> 2;
    const int mt = wrp & 3;
    const int r0 = mt * 16 + g;
    {
        float4 sacc[7];
        #pragma unroll
        for (int n = 0; n < 7; n++) sacc[n] = make_float4(0.f, 0.f, 0.f, 0.f);
        #pragma unroll
        for (int kt = 0; kt < 2; kt++) {
            int kb = h * 32 + kt * 16;
            uint2 A0 = *(const uint2*)&smh[base + OFF_Q + r0 * SH + kb + 4 * tg];
            uint2 A1 = *(const uint2*)&smh[base + OFF_Q + (r0 + 8) * SH + kb + 4 * tg];
            #pragma unroll
            for (int n = 0; n < 7; n++) {
                uint2 Bn = *(const uint2*)&smh[base + OFF_K + (n * 8 + g) * SH + kb + 4 * tg];
                mma16(sacc[n], A0.x, A1.x, A0.y, A1.y, Bn.x, Bn.y);
            }
        }

        // register softmax; rows r0 (x,y) and r0+8 (z,w) live in this lane quad
        if (NTOK < 56) {
            #pragma unroll
            for (int n = 0; n < 7; n++) {
                int j0 = 8 * n + 2 * tg;
                if (j0 >= NTOK)     { sacc[n].x = -1e30f; sacc[n].z = -1e30f; }
                if (j0 + 1 >= NTOK) { sacc[n].y = -1e30f; sacc[n].w = -1e30f; }
            }
        }
        float mA = -1e30f, mB = -1e30f;
        #pragma unroll
        for (int n = 0; n < 7; n++) {
            mA = fmaxf(mA, fmaxf(sacc[n].x, sacc[n].y));
            mB = fmaxf(mB, fmaxf(sacc[n].z, sacc[n].w));
        }
        #pragma unroll
        for (int o = 1; o <= 2; o <<= 1) {
            mA = fmaxf(mA, __shfl_xor_sync(~0u, mA, o));
            mB = fmaxf(mB, __shfl_xor_sync(~0u, mB, o));
        }
        float sA = 0.f, sB = 0.f;
        #pragma unroll
        for (int n = 0; n < 7; n++) {
            sacc[n].x = __expf(sacc[n].x - mA);
            sacc[n].y = __expf(sacc[n].y - mA);
            sacc[n].z = __expf(sacc[n].z - mB);
            sacc[n].w = __expf(sacc[n].w - mB);
            sA += sacc[n].x + sacc[n].y;
            sB += sacc[n].z + sacc[n].w;
        }
        #pragma unroll
        for (int o = 1; o <= 2; o <<= 1) {
            sA += __shfl_xor_sync(~0u, sA, o);
            sB += __shfl_xor_sync(~0u, sB, o);
        }
        float iA = 1.0f / sA, iB = 1.0f / sB;

        // Pack P into PV A-fragment registers (scores C-frag == A-frag layout).
        uint32_t pA[7], pB[7];
        #pragma unroll
        for (int n = 0; n < 7; n++) {
            pA[n] = h2u(sacc[n].x * iA, sacc[n].y * iA);
            pB[n] = h2u(sacc[n].z * iB, sacc[n].w * iB);
        }

        // ---- attn @ V: B-frags via ldmatrix.trans on plain-layout V ----
        const int li  = lane & 7;
        const int grp = lane >> 3;
        float4 vacc[4];
        #pragma unroll
        for (int n = 0; n < 4; n++) vacc[n] = make_float4(0.f, 0.f, 0.f, 0.f);
        #pragma unroll
        for (int kt = 0; kt < 4; kt++) {
            int kb = kt * 16;
            int vrow = kb + ((grp & 1) << 3) + li;
            int vcol = h * 32 + ((grp >> 1) << 3);
            uint32_t addr = smem_u32 +
                            (uint32_t)(base + OFF_V + vrow * VS + vcol) * 2;
            uint32_t b00, b01, b10, b11;   // channels [h*32, h*32+16)
            ldsm_x4_t(b00, b01, b10, b11, addr);
            uint32_t b20, b21, b30, b31;   // channels [h*32+16, h*32+32)
            ldsm_x4_t(b20, b21, b30, b31, addr + 32);

            uint32_t a0 = pA[2 * kt], a1 = pB[2 * kt];
            uint32_t a2 = (2 * kt + 1 < 7) ? pA[2 * kt + 1] : 0u;  // j pad = 0
            uint32_t a3 = (2 * kt + 1 < 7) ? pB[2 * kt + 1] : 0u;
            mma16(vacc[0], a0, a1, a2, a3, b00, b01);
            mma16(vacc[1], a0, a1, a2, a3, b10, b11);
            mma16(vacc[2], a0, a1, a2, a3, b20, b21);
            mma16(vacc[3], a0, a1, a2, a3, b30, b31);
        }
        #pragma unroll
        for (int n = 0; n < 4; n++) {
            int pos = h * 32 + (n >> 1) * 16 + 4 * tg + 2 * (n & 1);
            *(uint32_t*)&smh[base + OFF_X + r0 * SH + pos]       = h2u(vacc[n].x, vacc[n].y);
            *(uint32_t*)&smh[base + OFF_X + (r0 + 8) * SH + pos] = h2u(vacc[n].z, vacc[n].w);
        }
    }
    cp_wait_all();     // proj weights landed
    __syncthreads();   // attn output + proj staging visible

    // ---- proj GEMM: attnout(64x128) @ Wproj(128x128) -> global ----
    {
        float4 acc[2][2];
        #pragma unroll
        for (int n = 0; n < 2; n++) {
            float b0 = projb[n0 + n * 8 + 2 * tg];
            float b1 = projb[n0 + n * 8 + 2 * tg + 1];
            acc[0][n] = make_float4(b0, b1, b0, b1);
            acc[1][n] = acc[0][n];
        }
        #pragma unroll 4
        for (int kt = 0; kt < 8; kt++) {
            int kb = kt * 16;
            uint2 A[2][2];
            #pragma unroll
            for (int m = 0; m < 2; m++) {
                int r = (mb + m) * 16 + g;
                A[m][0] = *(const uint2*)&smh[base + OFF_X + r * SH + kb + 4 * tg];
                A[m][1] = *(const uint2*)&smh[base + OFF_X + (r + 8) * SH + kb + 4 * tg];
            }
            uint2 B[2];
            #pragma unroll
            for (int n = 0; n < 2; n++) {
                int nn = n0 + n * 8 + g;
                B[n] = *(const uint2*)&smh[OFF_W + nn * WSH + kb + 4 * tg];
            }
            #pragma unroll
            for (int m = 0; m < 2; m++)
                #pragma unroll
                for (int n = 0; n < 2; n++)
                    mma16(acc[m][n], A[m][0].x, A[m][1].x, A[m][0].y, A[m][1].y,
                          B[n].x, B[n].y);
        }

        #pragma unroll
        for (int m = 0; m < 2; m++) {
            #pragma unroll
            for (int rr = 0; rr < 2; rr++) {
                int r = (mb + m) * 16 + g + rr * 8;
                if (r < NTOK) {
                    #pragma unroll
                    for (int n = 0; n < 2; n++) {
                        float2 val = rr ? make_float2(acc[m][n].z, acc[m][n].w)
                                        : make_float2(acc[m][n].x, acc[m][n].y);
                        size_t o = (size_t)tokidx[wh * 64 + r] * 128 + n0 + n * 8 + 2 * tg;
                        if (BRANCH == 0) {
                            *(float2*)&out[o] = val;
                        } else {
                            asm volatile("red.global.add.v2.f32 [%0], {%1, %2};"
                                         :: "l"(out + o), "f"(val.x), "f"(val.y)
                                         : "memory");
                        }
                    }
                }
            }
        }
    }
}

extern "C" void kernel_launch(void* const* d_in, const int* in_sizes, int n_in,
                              void* d_out, int out_size)
{
    const float* x         = (const float*)d_in[0];
    const float* qkv_w     = (const float*)d_in[1];
    const float* qkv_b     = (const float*)d_in[2];
    const float* qkv_th_w  = (const float*)d_in[3];
    const float* qkv_th_b  = (const float*)d_in[4];
    const float* qkv_tw_w  = (const float*)d_in[5];
    const float* qkv_tw_b  = (const float*)d_in[6];
    const float* proj_w    = (const float*)d_in[7];
    const float* proj_b    = (const float*)d_in[8];
    const float* proj_th_w = (const float*)d_in[9];
    const float* proj_th_b = (const float*)d_in[10];
    const float* proj_tw_w = (const float*)d_in[11];
    const float* proj_tw_b = (const float*)d_in[12];
    float* out = (float*)d_out;

    conv_weights<<<768, 256>>>(qkv_w, qkv_th_w, qkv_tw_w,
                               proj_w, proj_th_w, proj_tw_w);

    cudaFuncSetAttribute(win_attn2<0, 49>,
                         cudaFuncAttributeMaxDynamicSharedMemorySize, SMEM_BYTES);
    cudaFuncSetAttribute(win_attn2<1, 56>,
                         cudaFuncAttributeMaxDynamicSharedMemorySize, SMEM_BYTES);
    cudaFuncSetAttribute(win_attn2<2, 56>,
                         cudaFuncAttributeMaxDynamicSharedMemorySize, SMEM_BYTES);

    // 2 windows per CTA. xy writes every output once; th / tw via REDG.
    win_attn2<0, 49><<<2048, 1024, SMEM_BYTES>>>(x, qkv_b, proj_b, out);
    win_attn2<1, 56><<<1792, 1024, SMEM_BYTES>>>(x, qkv_th_b, proj_th_b, out);
    win_attn2<2, 56><<<1792, 1024, SMEM_BYTES>>>(x, qkv_tw_b, proj_tw_b, out);
}

// round 11
// speedup vs baseline: 1.0613x; 1.0322x over previous
#include <cuda_runtime.h>
#include <cuda_fp16.h>
#include <cstdint>

// Problem constants: B=8, D=8, H=W=56, C=128, 4 heads x 32, windows (8,7,7),
// all pads zero. xy: 4096 windows x 49 tok; th/tw: 3584 x 56.
//
// 2 windows per CTA (1024 thr), shared staged weight buffer, cp.async staging.
// ALL matrix fragments via ldmatrix (x4 / x2 / x4.trans) on PLAIN row-major
// smem with stride 136 halves (68 words = 4 mod 32 -> every LDSM phase is
// bank-conflict-free). No permuted layouts, minimal address ALU: per-lane
// LDSM base addresses computed once, inner loops add kt*32 bytes.
// P register-resident (scores C-frag == PV A-frag). th/tw accumulate via REDG.

static constexpr int SH   = 136;  // stride (halves) X/Q/K rows
static constexpr int WSH  = 136;  // stride staged weight rows
static constexpr int VS   = 136;  // stride V rows

static constexpr int OFF_X  = 0;                    // 64 x SH (x, later attn out)
static constexpr int OFF_Q  = OFF_X + 64 * SH;
static constexpr int OFF_K  = OFF_Q + 64 * SH;
static constexpr int OFF_V  = OFF_K + 64 * SH;
static constexpr int ACT_HALVES = OFF_V + 64 * VS;  // 34816
static constexpr int OFF_W  = 2 * ACT_HALVES;       // shared staged weights
static constexpr int TOT_HALVES = OFF_W + 128 * WSH;           // 87040
static constexpr int SMEM_BYTES = TOT_HALVES * 2 + 128 * 4;    // 174592 (1 CTA/SM)

// Pre-converted fp16 weights, PLAIN transposed: [n][k], row n contiguous in k.
__device__ __align__(16) __half g_qkvwt[3][384 * 128];
__device__ __align__(16) __half g_projwt[3][128 * 128];

template <int BRANCH>
__device__ __forceinline__ int tok_index(int win, int tt) {
    if (BRANCH == 0) {                 // xy: (b, d, hb, wb) x (hh, ww)
        int b  = win >> 9;
        int d  = (win >> 6) & 7;
        int hb = (win >> 3) & 7;
        int wb = win & 7;
        int hh = tt / 7, wq = tt - hh * 7;
        return ((b * 8 + d) * 56 + hb * 7 + hh) * 56 + wb * 7 + wq;
    } else if (BRANCH == 1) {          // th: (b, hb, w) x (dd, hh)
        int b  = win / 448;
        int r  = win - b * 448;
        int hb = r / 56;
        int w  = r - hb * 56;
        int dd = tt / 7, hh = tt - dd * 7;
        return ((b * 8 + dd) * 56 + hb * 7 + hh) * 56 + w;
    } else {                           // tw: (b, h, wb) x (dd, ww)
        int b  = win / 448;
        int r  = win - b * 448;
        int h  = r >> 3;
        int wb = r & 7;
        int dd = tt / 7, wq = tt - dd * 7;
        return ((b * 8 + dd) * 56 + h) * 56 + wb * 7 + wq;
    }
}

// D += A(16x16) * B(16x8), f16 in, f32 accumulate.
__device__ __forceinline__ void mma16(float4& d, uint32_t a0, uint32_t a1,
                                      uint32_t a2, uint32_t a3,
                                      uint32_t b0, uint32_t b1) {
    asm volatile(
        "mma.sync.aligned.m16n8k16.row.col.f32.f16.f16.f32 "
        "{%0,%1,%2,%3}, {%4,%5,%6,%7}, {%8,%9}, {%0,%1,%2,%3};\n"
        : "+f"(d.x), "+f"(d.y), "+f"(d.z), "+f"(d.w)
        : "r"(a0), "r"(a1), "r"(a2), "r"(a3), "r"(b0), "r"(b1));
}

__device__ __forceinline__ void ldsm_x4(uint32_t& r0, uint32_t& r1,
                                        uint32_t& r2, uint32_t& r3,
                                        uint32_t addr) {
    asm volatile("ldmatrix.sync.aligned.m8n8.x4.shared.b16 {%0,%1,%2,%3}, [%4];"
                 : "=r"(r0), "=r"(r1), "=r"(r2), "=r"(r3) : "r"(addr));
}
__device__ __forceinline__ void ldsm_x2(uint32_t& r0, uint32_t& r1, uint32_t addr) {
    asm volatile("ldmatrix.sync.aligned.m8n8.x2.shared.b16 {%0,%1}, [%2];"
                 : "=r"(r0), "=r"(r1) : "r"(addr));
}
__device__ __forceinline__ void ldsm_x4_t(uint32_t& r0, uint32_t& r1,
                                          uint32_t& r2, uint32_t& r3,
                                          uint32_t addr) {
    asm volatile("ldmatrix.sync.aligned.m8n8.x4.trans.shared.b16 "
                 "{%0,%1,%2,%3}, [%4];"
                 : "=r"(r0), "=r"(r1), "=r"(r2), "=r"(r3) : "r"(addr));
}

__device__ __forceinline__ void cp16(uint32_t dst, const void* src) {
    asm volatile("cp.async.cg.shared.global [%0], [%1], 16;" :: "r"(dst), "l"(src));
}
__device__ __forceinline__ void cp_wait_all() {
    asm volatile("cp.async.commit_group;\n\tcp.async.wait_group 0;" ::: "memory");
}

__device__ __forceinline__ uint32_t h2u(float a, float b) {
    __half2 h = __floats2half2_rn(a, b);
    return *(uint32_t*)&h;
}

// ---------------- weight pre-conversion (plain transpose) ----------------
__global__ void conv_weights(const float* __restrict__ w0, const float* __restrict__ w1,
                             const float* __restrict__ w2, const float* __restrict__ p0,
                             const float* __restrict__ p1, const float* __restrict__ p2) {
    int tid = blockIdx.x * 256 + threadIdx.x;
    const int QK = 3 * 384 * 128;
    if (tid < QK) {
        int br  = tid / (384 * 128);
        int rem = tid - br * 384 * 128;
        int n = rem >> 7, k = rem & 127;
        const float* src = (br == 0) ? w0 : (br == 1 ? w1 : w2);
        g_qkvwt[br][rem] = __float2half_rn(src[k * 384 + n]);
    } else {
        int t2  = tid - QK;
        int br  = t2 / (128 * 128);
        int rem = t2 - br * 16384;
        int n = rem >> 7, k = rem & 127;
        const float* src = (br == 0) ? p0 : (br == 1 ? p1 : p2);
        g_projwt[br][rem] = __float2half_rn(src[k * 128 + n]);
    }
}

// ------------- fused window attention, TWO windows per CTA -------------
template <int BRANCH, int NTOK>
__global__ void __launch_bounds__(1024, 1)
win_attn2(const float* __restrict__ x,
          const float* __restrict__ qkvb, const float* __restrict__ projb,
          float* __restrict__ out)
{
    extern __shared__ __align__(16) __half smh[];
    int* tokidx = (int*)(smh + TOT_HALVES);
    const uint32_t smem_u32 = (uint32_t)__cvta_generic_to_shared(smh);

    const int t    = threadIdx.x;          // 0..1023
    const int wh   = t >> 9;               // window half 0/1
    const int tl   = t & 511;
    const int lane = t & 31;
    const int wrp  = tl >> 5;              // local warp 0..15
    const int g    = lane >> 2;
    const int tg   = lane & 3;
    const int win  = blockIdx.x * 2 + wh;
    const int base = wh * ACT_HALVES;

    // ldmatrix per-lane address components
    const int aRow = lane & 15;                       // A-frag: row within 16
    const int aCol = (lane >> 4) << 3;                // A-frag: k col 0/8
    const int bRow = (lane & 7) + ((lane >> 4) << 3); // B-frag: n row within 16
    const int bCol = ((lane >> 3) & 1) << 3;          // B-frag: k col 0/8

    if (tl < NTOK) tokidx[wh * 64 + tl] = tok_index<BRANCH>(win, tl);

    // ---- x -> X (fp16, plain rows), pad rows zeroed ----
    for (int idx = tl; idx < 64 * 32; idx += 512) {
        int r = idx >> 5, q = idx & 31;
        uint2 u = make_uint2(0u, 0u);
        if (r < NTOK) {
            float4 v = *(const float4*)
                (x + (size_t)tok_index<BRANCH>(win, r) * 128 + q * 4);
            u.x = h2u(v.x, v.y);
            u.y = h2u(v.z, v.w);
        }
        *(uint2*)&smh[base + OFF_X + r * SH + q * 4] = u;
    }
    // (x visibility covered by the first staging barrier below)

    const int mb = (wrp & 1) * 2;        // m-tiles {mb, mb+1}
    const int n0 = (wrp >> 1) * 16;      // n columns [n0, n0+16)
    const float qscale = 0.1767766952966369f;

    // Per-lane LDSM base addresses (bytes); inner loops add kt*32.
    const uint32_t xA0 = smem_u32 +
        (uint32_t)(base + OFF_X + (mb * 16 + aRow) * SH + aCol) * 2;
    const uint32_t xA1 = xA0 + 16u * SH * 2u;
    const uint32_t wB  = smem_u32 + (uint32_t)(OFF_W + (n0 + bRow) * WSH + bCol) * 2;

    // ---- QKV GEMM: X(64x128) @ W chunk(128x128), chunks q,k,v ----
    #pragma unroll 1
    for (int cc = 0; cc < 3; cc++) {
        const __half* wsrc = g_qkvwt[BRANCH] + cc * 128 * 128;
        for (int idx = t; idx < 128 * 16; idx += 1024) {   // whole CTA stages once
            int rw = idx >> 4, c8 = idx & 15;
            cp16(smem_u32 + (uint32_t)(OFF_W + rw * WSH + c8 * 8) * 2,
                 wsrc + rw * 128 + c8 * 8);
        }
        cp_wait_all();
        __syncthreads();

        float4 acc[2][2];
        #pragma unroll
        for (int n = 0; n < 2; n++) {
            float b0 = qkvb[cc * 128 + n0 + n * 8 + 2 * tg];
            float b1 = qkvb[cc * 128 + n0 + n * 8 + 2 * tg + 1];
            acc[0][n] = make_float4(b0, b1, b0, b1);
            acc[1][n] = acc[0][n];
        }

        #pragma unroll 4
        for (int kt = 0; kt < 8; kt++) {
            uint32_t koff = kt * 32u;
            uint32_t A0[4], A1[4], Bv[4];
            ldsm_x4(A0[0], A0[1], A0[2], A0[3], xA0 + koff);
            ldsm_x4(A1[0], A1[1], A1[2], A1[3], xA1 + koff);
            ldsm_x4(Bv[0], Bv[1], Bv[2], Bv[3], wB + koff);
            mma16(acc[0][0], A0[0], A0[1], A0[2], A0[3], Bv[0], Bv[1]);
            mma16(acc[0][1], A0[0], A0[1], A0[2], A0[3], Bv[2], Bv[3]);
            mma16(acc[1][0], A1[0], A1[1], A1[2], A1[3], Bv[0], Bv[1]);
            mma16(acc[1][1], A1[0], A1[1], A1[2], A1[3], Bv[2], Bv[3]);
        }

        if (cc < 2) {   // q or k: plain layout stores
            const int dst = base + ((cc == 0) ? OFF_Q : OFF_K);
            const float mul = (cc == 0) ? qscale : 1.0f;
            #pragma unroll
            for (int m = 0; m < 2; m++) {
                int r = (mb + m) * 16 + g;
                #pragma unroll
                for (int n = 0; n < 2; n++) {
                    int c = n0 + n * 8 + 2 * tg;
                    *(uint32_t*)&smh[dst + r * SH + c] =
                        h2u(acc[m][n].x * mul, acc[m][n].y * mul);
                    *(uint32_t*)&smh[dst + (r + 8) * SH + c] =
                        h2u(acc[m][n].z * mul, acc[m][n].w * mul);
                }
            }
        } else {        // v: plain layout
            #pragma unroll
            for (int m = 0; m < 2; m++) {
                int r = (mb + m) * 16 + g;
                #pragma unroll
                for (int n = 0; n < 2; n++) {
                    int c = n0 + n * 8 + 2 * tg;
                    *(uint32_t*)&smh[base + OFF_V + r * VS + c] =
                        h2u(acc[m][n].x, acc[m][n].y);
                    *(uint32_t*)&smh[base + OFF_V + (r + 8) * VS + c] =
                        h2u(acc[m][n].z, acc[m][n].w);
                }
            }
        }
        __syncthreads();   // OFF_W consumption done before restage
    }

    // Prefetch proj weights (cp.async overlaps with scores/attn compute).
    {
        const __half* psrc = g_projwt[BRANCH];
        for (int idx = t; idx < 128 * 16; idx += 1024) {
            int rw = idx >> 4, c8 = idx & 15;
            cp16(smem_u32 + (uint32_t)(OFF_W + rw * WSH + c8 * 8) * 2,
                 psrc + rw * 128 + c8 * 8);
        }
    }

    // ---- scores + softmax + P@V, P fully register-resident ----
    const int h  = wrp >> 2;
    const int mt = wrp & 3;
    const int r0 = mt * 16 + g;
    {
        const uint32_t qA = smem_u32 +
            (uint32_t)(base + OFF_Q + (mt * 16 + aRow) * SH + h * 32 + aCol) * 2;
        uint32_t kB[3];
        #pragma unroll
        for (int nn = 0; nn < 3; nn++)
            kB[nn] = smem_u32 +
                (uint32_t)(base + OFF_K + (nn * 16 + bRow) * SH + h * 32 + bCol) * 2;
        const uint32_t kB2 = smem_u32 +
            (uint32_t)(base + OFF_K + (48 + (lane & 7)) * SH + h * 32 + bCol) * 2;

        float4 sacc[7];
        #pragma unroll
        for (int n = 0; n < 7; n++) sacc[n] = make_float4(0.f, 0.f, 0.f, 0.f);
        #pragma unroll
        for (int kt = 0; kt < 2; kt++) {
            uint32_t koff = kt * 32u;
            uint32_t Aq[4];
            ldsm_x4(Aq[0], Aq[1], Aq[2], Aq[3], qA + koff);
            #pragma unroll
            for (int nn = 0; nn < 3; nn++) {
                uint32_t Bk[4];
                ldsm_x4(Bk[0], Bk[1], Bk[2], Bk[3], kB[nn] + koff);
                mma16(sacc[2 * nn],     Aq[0], Aq[1], Aq[2], Aq[3], Bk[0], Bk[1]);
                mma16(sacc[2 * nn + 1], Aq[0], Aq[1], Aq[2], Aq[3], Bk[2], Bk[3]);
            }
            uint32_t b0, b1;
            ldsm_x2(b0, b1, kB2 + koff);
            mma16(sacc[6], Aq[0], Aq[1], Aq[2], Aq[3], b0, b1);
        }

        // register softmax; rows r0 (x,y) and r0+8 (z,w) live in this lane quad
        if (NTOK < 56) {
            #pragma unroll
            for (int n = 0; n < 7; n++) {
                int j0 = 8 * n + 2 * tg;
                if (j0 >= NTOK)     { sacc[n].x = -1e30f; sacc[n].z = -1e30f; }
                if (j0 + 1 >= NTOK) { sacc[n].y = -1e30f; sacc[n].w = -1e30f; }
            }
        }
        float mA = -1e30f, mB = -1e30f;
        #pragma unroll
        for (int n = 0; n < 7; n++) {
            mA = fmaxf(mA, fmaxf(sacc[n].x, sacc[n].y));
            mB = fmaxf(mB, fmaxf(sacc[n].z, sacc[n].w));
        }
        #pragma unroll
        for (int o = 1; o <= 2; o <<= 1) {
            mA = fmaxf(mA, __shfl_xor_sync(~0u, mA, o));
            mB = fmaxf(mB, __shfl_xor_sync(~0u, mB, o));
        }
        float sA = 0.f, sB = 0.f;
        #pragma unroll
        for (int n = 0; n < 7; n++) {
            sacc[n].x = __expf(sacc[n].x - mA);
            sacc[n].y = __expf(sacc[n].y - mA);
            sacc[n].z = __expf(sacc[n].z - mB);
            sacc[n].w = __expf(sacc[n].w - mB);
            sA += sacc[n].x + sacc[n].y;
            sB += sacc[n].z + sacc[n].w;
        }
        #pragma unroll
        for (int o = 1; o <= 2; o <<= 1) {
            sA += __shfl_xor_sync(~0u, sA, o);
            sB += __shfl_xor_sync(~0u, sB, o);
        }
        float iA = 1.0f / sA, iB = 1.0f / sB;

        // Pack P into PV A-fragment registers (scores C-frag == A-frag layout).
        uint32_t pA[7], pB[7];
        #pragma unroll
        for (int n = 0; n < 7; n++) {
            pA[n] = h2u(sacc[n].x * iA, sacc[n].y * iA);
            pB[n] = h2u(sacc[n].z * iB, sacc[n].w * iB);
        }

        // ---- attn @ V: B-frags via ldmatrix.trans on plain-layout V ----
        const int li  = lane & 7;
        const int grp = lane >> 3;
        float4 vacc[4];
        #pragma unroll
        for (int n = 0; n < 4; n++) vacc[n] = make_float4(0.f, 0.f, 0.f, 0.f);
        const uint32_t vB = smem_u32 + (uint32_t)
            (base + OFF_V + (((grp & 1) << 3) + li) * VS + h * 32 + ((grp >> 1) << 3)) * 2;
        #pragma unroll
        for (int kt = 0; kt < 4; kt++) {
            uint32_t addr = vB + (uint32_t)(kt * 16 * VS) * 2;
            uint32_t b00, b01, b10, b11;   // channels [h*32, h*32+16)
            ldsm_x4_t(b00, b01, b10, b11, addr);
            uint32_t b20, b21, b30, b31;   // channels [h*32+16, h*32+32)
            ldsm_x4_t(b20, b21, b30, b31, addr + 32);

            uint32_t a0 = pA[2 * kt], a1 = pB[2 * kt];
            uint32_t a2 = (2 * kt + 1 < 7) ? pA[2 * kt + 1] : 0u;  // j pad = 0
            uint32_t a3 = (2 * kt + 1 < 7) ? pB[2 * kt + 1] : 0u;
            mma16(vacc[0], a0, a1, a2, a3, b00, b01);
            mma16(vacc[1], a0, a1, a2, a3, b10, b11);
            mma16(vacc[2], a0, a1, a2, a3, b20, b21);
            mma16(vacc[3], a0, a1, a2, a3, b30, b31);
        }
        #pragma unroll
        for (int n = 0; n < 4; n++) {
            int c = h * 32 + n * 8 + 2 * tg;
            *(uint32_t*)&smh[base + OFF_X + r0 * SH + c]       = h2u(vacc[n].x, vacc[n].y);
            *(uint32_t*)&smh[base + OFF_X + (r0 + 8) * SH + c] = h2u(vacc[n].z, vacc[n].w);
        }
    }
    cp_wait_all();     // proj weights landed
    __syncthreads();   // attn output + proj staging visible

    // ---- proj GEMM: attnout(64x128) @ Wproj(128x128) -> global ----
    {
        float4 acc[2][2];
        #pragma unroll
        for (int n = 0; n < 2; n++) {
            float b0 = projb[n0 + n * 8 + 2 * tg];
            float b1 = projb[n0 + n * 8 + 2 * tg + 1];
            acc[0][n] = make_float4(b0, b1, b0, b1);
            acc[1][n] = acc[0][n];
        }
        #pragma unroll 4
        for (int kt = 0; kt < 8; kt++) {
            uint32_t koff = kt * 32u;
            uint32_t A0[4], A1[4], Bv[4];
            ldsm_x4(A0[0], A0[1], A0[2], A0[3], xA0 + koff);
            ldsm_x4(A1[0], A1[1], A1[2], A1[3], xA1 + koff);
            ldsm_x4(Bv[0], Bv[1], Bv[2], Bv[3], wB + koff);
            mma16(acc[0][0], A0[0], A0[1], A0[2], A0[3], Bv[0], Bv[1]);
            mma16(acc[0][1], A0[0], A0[1], A0[2], A0[3], Bv[2], Bv[3]);
            mma16(acc[1][0], A1[0], A1[1], A1[2], A1[3], Bv[0], Bv[1]);
            mma16(acc[1][1], A1[0], A1[1], A1[2], A1[3], Bv[2], Bv[3]);
        }

        #pragma unroll
        for (int m = 0; m < 2; m++) {
            #pragma unroll
            for (int rr = 0; rr < 2; rr++) {
                int r = (mb + m) * 16 + g + rr * 8;
                if (r < NTOK) {
                    #pragma unroll
                    for (int n = 0; n < 2; n++) {
                        float2 val = rr ? make_float2(acc[m][n].z, acc[m][n].w)
                                        : make_float2(acc[m][n].x, acc[m][n].y);
                        size_t o = (size_t)tokidx[wh * 64 + r] * 128 + n0 + n * 8 + 2 * tg;
                        if (BRANCH == 0) {
                            *(float2*)&out[o] = val;
                        } else {
                            asm volatile("red.global.add.v2.f32 [%0], {%1, %2};"
                                         :: "l"(out + o), "f"(val.x), "f"(val.y)
                                         : "memory");
                        }
                    }
                }
            }
        }
    }
}

extern "C" void kernel_launch(void* const* d_in, const int* in_sizes, int n_in,
                              void* d_out, int out_size)
{
    const float* x         = (const float*)d_in[0];
    const float* qkv_w     = (const float*)d_in[1];
    const float* qkv_b     = (const float*)d_in[2];
    const float* qkv_th_w  = (const float*)d_in[3];
    const float* qkv_th_b  = (const float*)d_in[4];
    const float* qkv_tw_w  = (const float*)d_in[5];
    const float* qkv_tw_b  = (const float*)d_in[6];
    const float* proj_w    = (const float*)d_in[7];
    const float* proj_b    = (const float*)d_in[8];
    const float* proj_th_w = (const float*)d_in[9];
    const float* proj_th_b = (const float*)d_in[10];
    const float* proj_tw_w = (const float*)d_in[11];
    const float* proj_tw_b = (const float*)d_in[12];
    float* out = (float*)d_out;

    conv_weights<<<768, 256>>>(qkv_w, qkv_th_w, qkv_tw_w,
                               proj_w, proj_th_w, proj_tw_w);

    cudaFuncSetAttribute(win_attn2<0, 49>,
                         cudaFuncAttributeMaxDynamicSharedMemorySize, SMEM_BYTES);
    cudaFuncSetAttribute(win_attn2<1, 56>,
                         cudaFuncAttributeMaxDynamicSharedMemorySize, SMEM_BYTES);
    cudaFuncSetAttribute(win_attn2<2, 56>,
                         cudaFuncAttributeMaxDynamicSharedMemorySize, SMEM_BYTES);

    // 2 windows per CTA. xy writes every output once; th / tw via REDG.
    win_attn2<0, 49><<<2048, 1024, SMEM_BYTES>>>(x, qkv_b, proj_b, out);
    win_attn2<1, 56><<<1792, 1024, SMEM_BYTES>>>(x, qkv_th_b, proj_th_b, out);
    win_attn2<2, 56><<<1792, 1024, SMEM_BYTES>>>(x, qkv_tw_b, proj_tw_b, out);
}

// round 12
// speedup vs baseline: 1.0850x; 1.0224x over previous
#include <cuda_runtime.h>
#include <cuda_fp16.h>
#include <cstdint>

// Problem constants: B=8, D=8, H=W=56, C=128, 4 heads x 32, windows (8,7,7),
// all pads zero. xy: 4096 windows x 49 tok; th/tw: 3584 x 56.
//
// 2 windows per CTA (1024 thr). ldmatrix everywhere on plain row-major smem
// (stride 136 halves -> conflict-free LDSM). P register-resident.
// NEW: double-buffered, software-pipelined cp.async weight staging (q->buf0,
// k->buf1 issued before x-load; v restaged into buf0 behind k-compute; proj
// into buf1 behind scores/PV) -> staging latency hidden. th+tw merged into
// ONE launch (both REDG, commutative) -> single scheduling tail.

static constexpr int SH   = 136;  // stride (halves) X/Q/K rows
static constexpr int WSH  = 136;  // stride staged weight rows
static constexpr int VS   = 136;  // stride V rows

static constexpr int OFF_X  = 0;                    // 64 x SH (x, later attn out)
static constexpr int OFF_Q  = OFF_X + 64 * SH;
static constexpr int OFF_K  = OFF_Q + 64 * SH;
static constexpr int OFF_V  = OFF_K + 64 * SH;
static constexpr int ACT_HALVES = OFF_V + 64 * VS;  // 34816
static constexpr int OFF_W0 = 2 * ACT_HALVES;       // weight buffer 0
static constexpr int OFF_W1 = OFF_W0 + 128 * WSH;   // weight buffer 1
static constexpr int TOT_HALVES = OFF_W1 + 128 * WSH;          // 104448
static constexpr int SMEM_BYTES = TOT_HALVES * 2 + 128 * 4;    // 209408 (1 CTA/SM)

// Pre-converted fp16 weights, PLAIN transposed: [n][k].
__device__ __align__(16) __half g_qkvwt[3][384 * 128];
__device__ __align__(16) __half g_projwt[3][128 * 128];

template <int BRANCH>
__device__ __forceinline__ int tok_index(int win, int tt) {
    if (BRANCH == 0) {                 // xy: (b, d, hb, wb) x (hh, ww)
        int b  = win >> 9;
        int d  = (win >> 6) & 7;
        int hb = (win >> 3) & 7;
        int wb = win & 7;
        int hh = tt / 7, wq = tt - hh * 7;
        return ((b * 8 + d) * 56 + hb * 7 + hh) * 56 + wb * 7 + wq;
    } else if (BRANCH == 1) {          // th: (b, hb, w) x (dd, hh)
        int b  = win / 448;
        int r  = win - b * 448;
        int hb = r / 56;
        int w  = r - hb * 56;
        int dd = tt / 7, hh = tt - dd * 7;
        return ((b * 8 + dd) * 56 + hb * 7 + hh) * 56 + w;
    } else {                           // tw: (b, h, wb) x (dd, ww)
        int b  = win / 448;
        int r  = win - b * 448;
        int h  = r >> 3;
        int wb = r & 7;
        int dd = tt / 7, wq = tt - dd * 7;
        return ((b * 8 + dd) * 56 + h) * 56 + wb * 7 + wq;
    }
}

__device__ __forceinline__ void mma16(float4& d, uint32_t a0, uint32_t a1,
                                      uint32_t a2, uint32_t a3,
                                      uint32_t b0, uint32_t b1) {
    asm volatile(
        "mma.sync.aligned.m16n8k16.row.col.f32.f16.f16.f32 "
        "{%0,%1,%2,%3}, {%4,%5,%6,%7}, {%8,%9}, {%0,%1,%2,%3};\n"
        : "+f"(d.x), "+f"(d.y), "+f"(d.z), "+f"(d.w)
        : "r"(a0), "r"(a1), "r"(a2), "r"(a3), "r"(b0), "r"(b1));
}

__device__ __forceinline__ void ldsm_x4(uint32_t& r0, uint32_t& r1,
                                        uint32_t& r2, uint32_t& r3, uint32_t addr) {
    asm volatile("ldmatrix.sync.aligned.m8n8.x4.shared.b16 {%0,%1,%2,%3}, [%4];"
                 : "=r"(r0), "=r"(r1), "=r"(r2), "=r"(r3) : "r"(addr));
}
__device__ __forceinline__ void ldsm_x2(uint32_t& r0, uint32_t& r1, uint32_t addr) {
    asm volatile("ldmatrix.sync.aligned.m8n8.x2.shared.b16 {%0,%1}, [%2];"
                 : "=r"(r0), "=r"(r1) : "r"(addr));
}
__device__ __forceinline__ void ldsm_x4_t(uint32_t& r0, uint32_t& r1,
                                          uint32_t& r2, uint32_t& r3, uint32_t addr) {
    asm volatile("ldmatrix.sync.aligned.m8n8.x4.trans.shared.b16 {%0,%1,%2,%3}, [%4];"
                 : "=r"(r0), "=r"(r1), "=r"(r2), "=r"(r3) : "r"(addr));
}

__device__ __forceinline__ void cp16(uint32_t dst, const void* src) {
    asm volatile("cp.async.cg.shared.global [%0], [%1], 16;" :: "r"(dst), "l"(src));
}
__device__ __forceinline__ void cp_commit() {
    asm volatile("cp.async.commit_group;" ::: "memory");
}
template <int N>
__device__ __forceinline__ void cp_wait() {
    asm volatile("cp.async.wait_group %0;" :: "n"(N) : "memory");
}

__device__ __forceinline__ uint32_t h2u(float a, float b) {
    __half2 h = __floats2half2_rn(a, b);
    return *(uint32_t*)&h;
}

// ---------------- weight pre-conversion (plain transpose) ----------------
__global__ void conv_weights(const float* __restrict__ w0, const float* __restrict__ w1,
                             const float* __restrict__ w2, const float* __restrict__ p0,
                             const float* __restrict__ p1, const float* __restrict__ p2) {
    int tid = blockIdx.x * 256 + threadIdx.x;
    const int QK = 3 * 384 * 128;
    if (tid < QK) {
        int br  = tid / (384 * 128);
        int rem = tid - br * 384 * 128;
        int n = rem >> 7, k = rem & 127;
        const float* src = (br == 0) ? w0 : (br == 1 ? w1 : w2);
        g_qkvwt[br][rem] = __float2half_rn(src[k * 384 + n]);
    } else {
        int t2  = tid - QK;
        int br  = t2 / (128 * 128);
        int rem = t2 - br * 16384;
        int n = rem >> 7, k = rem & 127;
        const float* src = (br == 0) ? p0 : (br == 1 ? p1 : p2);
        g_projwt[br][rem] = __float2half_rn(src[k * 128 + n]);
    }
}

// ------------- fused window attention body, TWO windows per CTA -------------
template <int BRANCH, int NTOK>
__device__ __forceinline__ void
win_body(int cta, const float* __restrict__ x,
         const float* __restrict__ qkvb, const float* __restrict__ projb,
         float* __restrict__ out)
{
    extern __shared__ __align__(16) __half smh[];
    int* tokidx = (int*)(smh + TOT_HALVES);
    const uint32_t smem_u32 = (uint32_t)__cvta_generic_to_shared(smh);

    const int t    = threadIdx.x;          // 0..1023
    const int wh   = t >> 9;               // window half 0/1
    const int tl   = t & 511;
    const int lane = t & 31;
    const int wrp  = tl >> 5;              // local warp 0..15
    const int g    = lane >> 2;
    const int tg   = lane & 3;
    const int win  = cta * 2 + wh;
    const int base = wh * ACT_HALVES;

    // ldmatrix per-lane address components
    const int aRow = lane & 15;
    const int aCol = (lane >> 4) << 3;
    const int bRow = (lane & 7) + ((lane >> 4) << 3);
    const int bCol = ((lane >> 3) & 1) << 3;

    // ---- stage q->buf0 (g0), k->buf1 (g1) BEFORE x-load ----
    {
        const __half* wq = g_qkvwt[BRANCH];
        const __half* wk = g_qkvwt[BRANCH] + 128 * 128;
        for (int idx = t; idx < 128 * 16; idx += 1024) {
            int rw = idx >> 4, c8 = idx & 15;
            cp16(smem_u32 + (uint32_t)(OFF_W0 + rw * WSH + c8 * 8) * 2,
                 wq + rw * 128 + c8 * 8);
        }
        cp_commit();                                   // g0 = q
        for (int idx = t; idx < 128 * 16; idx += 1024) {
            int rw = idx >> 4, c8 = idx & 15;
            cp16(smem_u32 + (uint32_t)(OFF_W1 + rw * WSH + c8 * 8) * 2,
                 wk + rw * 128 + c8 * 8);
        }
        cp_commit();                                   // g1 = k
    }

    if (tl < NTOK) tokidx[wh * 64 + tl] = tok_index<BRANCH>(win, tl);

    // ---- x -> X (fp16, plain rows), pad rows zeroed ----
    for (int idx = tl; idx < 64 * 32; idx += 512) {
        int r = idx >> 5, q = idx & 31;
        uint2 u = make_uint2(0u, 0u);
        if (r < NTOK) {
            float4 v = *(const float4*)
                (x + (size_t)tok_index<BRANCH>(win, r) * 128 + q * 4);
            u.x = h2u(v.x, v.y);
            u.y = h2u(v.z, v.w);
        }
        *(uint2*)&smh[base + OFF_X + r * SH + q * 4] = u;
    }

    const int mb = (wrp & 1) * 2;        // m-tiles {mb, mb+1}
    const int n0 = (wrp >> 1) * 16;      // n columns [n0, n0+16)
    const float qscale = 0.1767766952966369f;

    const uint32_t xA0 = smem_u32 +
        (uint32_t)(base + OFF_X + (mb * 16 + aRow) * SH + aCol) * 2;
    const uint32_t xA1 = xA0 + 16u * SH * 2u;
    const uint32_t wB0 = smem_u32 + (uint32_t)(OFF_W0 + (n0 + bRow) * WSH + bCol) * 2;
    const uint32_t wB1 = smem_u32 + (uint32_t)(OFF_W1 + (n0 + bRow) * WSH + bCol) * 2;

    // ---- q chunk (buf0) ----
    cp_wait<1>();        // g0 (q weights) landed
    __syncthreads();     // B1: x + q weights visible
    {
        float4 acc[2][2];
        #pragma unroll
        for (int n = 0; n < 2; n++) {
            float b0 = qkvb[n0 + n * 8 + 2 * tg];
            float b1 = qkvb[n0 + n * 8 + 2 * tg + 1];
            acc[0][n] = make_float4(b0, b1, b0, b1);
            acc[1][n] = acc[0][n];
        }
        #pragma unroll 4
        for (int kt = 0; kt < 8; kt++) {
            uint32_t koff = kt * 32u;
            uint32_t A0[4], A1[4], Bv[4];
            ldsm_x4(A0[0], A0[1], A0[2], A0[3], xA0 + koff);
            ldsm_x4(A1[0], A1[1], A1[2], A1[3], xA1 + koff);
            ldsm_x4(Bv[0], Bv[1], Bv[2], Bv[3], wB0 + koff);
            mma16(acc[0][0], A0[0], A0[1], A0[2], A0[3], Bv[0], Bv[1]);
            mma16(acc[0][1], A0[0], A0[1], A0[2], A0[3], Bv[2], Bv[3]);
            mma16(acc[1][0], A1[0], A1[1], A1[2], A1[3], Bv[0], Bv[1]);
            mma16(acc[1][1], A1[0], A1[1], A1[2], A1[3], Bv[2], Bv[3]);
        }
        #pragma unroll
        for (int m = 0; m < 2; m++) {
            int r = (mb + m) * 16 + g;
            #pragma unroll
            for (int n = 0; n < 2; n++) {
                int c = n0 + n * 8 + 2 * tg;
                *(uint32_t*)&smh[base + OFF_Q + r * SH + c] =
                    h2u(acc[m][n].x * qscale, acc[m][n].y * qscale);
                *(uint32_t*)&smh[base + OFF_Q + (r + 8) * SH + c] =
                    h2u(acc[m][n].z * qscale, acc[m][n].w * qscale);
            }
        }
    }
    __syncthreads();     // B2: buf0 free for restage

    // ---- restage v->buf0 (g2), then k chunk (buf1) ----
    {
        const __half* wv = g_qkvwt[BRANCH] + 2 * 128 * 128;
        for (int idx = t; idx < 128 * 16; idx += 1024) {
            int rw = idx >> 4, c8 = idx & 15;
            cp16(smem_u32 + (uint32_t)(OFF_W0 + rw * WSH + c8 * 8) * 2,
                 wv + rw * 128 + c8 * 8);
        }
        cp_commit();     // g2 = v
    }
    cp_wait<1>();        // g1 (k weights) landed (g2 may be pending)
    __syncthreads();     // B3: k weights visible
    {
        float4 acc[2][2];
        #pragma unroll
        for (int n = 0; n < 2; n++) {
            float b0 = qkvb[128 + n0 + n * 8 + 2 * tg];
            float b1 = qkvb[128 + n0 + n * 8 + 2 * tg + 1];
            acc[0][n] = make_float4(b0, b1, b0, b1);
            acc[1][n] = acc[0][n];
        }
        #pragma unroll 4
        for (int kt = 0; kt < 8; kt++) {
            uint32_t koff = kt * 32u;
            uint32_t A0[4], A1[4], Bv[4];
            ldsm_x4(A0[0], A0[1], A0[2], A0[3], xA0 + koff);
            ldsm_x4(A1[0], A1[1], A1[2], A1[3], xA1 + koff);
            ldsm_x4(Bv[0], Bv[1], Bv[2], Bv[3], wB1 + koff);
            mma16(acc[0][0], A0[0], A0[1], A0[2], A0[3], Bv[0], Bv[1]);
            mma16(acc[0][1], A0[0], A0[1], A0[2], A0[3], Bv[2], Bv[3]);
            mma16(acc[1][0], A1[0], A1[1], A1[2], A1[3], Bv[0], Bv[1]);
            mma16(acc[1][1], A1[0], A1[1], A1[2], A1[3], Bv[2], Bv[3]);
        }
        #pragma unroll
        for (int m = 0; m < 2; m++) {
            int r = (mb + m) * 16 + g;
            #pragma unroll
            for (int n = 0; n < 2; n++) {
                int c = n0 + n * 8 + 2 * tg;
                *(uint32_t*)&smh[base + OFF_K + r * SH + c] =
                    h2u(acc[m][n].x, acc[m][n].y);
                *(uint32_t*)&smh[base + OFF_K + (r + 8) * SH + c] =
                    h2u(acc[m][n].z, acc[m][n].w);
            }
        }
    }

    // ---- v chunk (buf0, restaged) ----
    cp_wait<0>();        // g2 (v weights) landed
    __syncthreads();     // B4: v weights visible (k-compute done everywhere)
    {
        float4 acc[2][2];
        #pragma unroll
        for (int n = 0; n < 2; n++) {
            float b0 = qkvb[256 + n0 + n * 8 + 2 * tg];
            float b1 = qkvb[256 + n0 + n * 8 + 2 * tg + 1];
            acc[0][n] = make_float4(b0, b1, b0, b1);
            acc[1][n] = acc[0][n];
        }
        #pragma unroll 4
        for (int kt = 0; kt < 8; kt++) {
            uint32_t koff = kt * 32u;
            uint32_t A0[4], A1[4], Bv[4];
            ldsm_x4(A0[0], A0[1], A0[2], A0[3], xA0 + koff);
            ldsm_x4(A1[0], A1[1], A1[2], A1[3], xA1 + koff);
            ldsm_x4(Bv[0], Bv[1], Bv[2], Bv[3], wB0 + koff);
            mma16(acc[0][0], A0[0], A0[1], A0[2], A0[3], Bv[0], Bv[1]);
            mma16(acc[0][1], A0[0], A0[1], A0[2], A0[3], Bv[2], Bv[3]);
            mma16(acc[1][0], A1[0], A1[1], A1[2], A1[3], Bv[0], Bv[1]);
            mma16(acc[1][1], A1[0], A1[1], A1[2], A1[3], Bv[2], Bv[3]);
        }
        #pragma unroll
        for (int m = 0; m < 2; m++) {
            int r = (mb + m) * 16 + g;
            #pragma unroll
            for (int n = 0; n < 2; n++) {
                int c = n0 + n * 8 + 2 * tg;
                *(uint32_t*)&smh[base + OFF_V + r * VS + c] =
                    h2u(acc[m][n].x, acc[m][n].y);
                *(uint32_t*)&smh[base + OFF_V + (r + 8) * VS + c] =
                    h2u(acc[m][n].z, acc[m][n].w);
            }
        }
    }
    __syncthreads();     // B5: Q, K, V visible; buf1 free

    // ---- restage proj->buf1 (g3), overlapped with scores/PV ----
    {
        const __half* psrc = g_projwt[BRANCH];
        for (int idx = t; idx < 128 * 16; idx += 1024) {
            int rw = idx >> 4, c8 = idx & 15;
            cp16(smem_u32 + (uint32_t)(OFF_W1 + rw * WSH + c8 * 8) * 2,
                 psrc + rw * 128 + c8 * 8);
        }
        cp_commit();     // g3 = proj
    }

    // ---- scores + softmax + P@V, P fully register-resident ----
    const int h  = wrp >> 2;
    const int mt = wrp & 3;
    const int r0 = mt * 16 + g;
    {
        const uint32_t qA = smem_u32 +
            (uint32_t)(base + OFF_Q + (mt * 16 + aRow) * SH + h * 32 + aCol) * 2;
        uint32_t kB[3];
        #pragma unroll
        for (int nn = 0; nn < 3; nn++)
            kB[nn] = smem_u32 +
                (uint32_t)(base + OFF_K + (nn * 16 + bRow) * SH + h * 32 + bCol) * 2;
        const uint32_t kB2 = smem_u32 +
            (uint32_t)(base + OFF_K + (48 + (lane & 7)) * SH + h * 32 + bCol) * 2;

        float4 sacc[7];
        #pragma unroll
        for (int n = 0; n < 7; n++) sacc[n] = make_float4(0.f, 0.f, 0.f, 0.f);
        #pragma unroll
        for (int kt = 0; kt < 2; kt++) {
            uint32_t koff = kt * 32u;
            uint32_t Aq[4];
            ldsm_x4(Aq[0], Aq[1], Aq[2], Aq[3], qA + koff);
            #pragma unroll
            for (int nn = 0; nn < 3; nn++) {
                uint32_t Bk[4];
                ldsm_x4(Bk[0], Bk[1], Bk[2], Bk[3], kB[nn] + koff);
                mma16(sacc[2 * nn],     Aq[0], Aq[1], Aq[2], Aq[3], Bk[0], Bk[1]);
                mma16(sacc[2 * nn + 1], Aq[0], Aq[1], Aq[2], Aq[3], Bk[2], Bk[3]);
            }
            uint32_t b0, b1;
            ldsm_x2(b0, b1, kB2 + koff);
            mma16(sacc[6], Aq[0], Aq[1], Aq[2], Aq[3], b0, b1);
        }

        if (NTOK < 56) {
            #pragma unroll
            for (int n = 0; n < 7; n++) {
                int j0 = 8 * n + 2 * tg;
                if (j0 >= NTOK)     { sacc[n].x = -1e30f; sacc[n].z = -1e30f; }
                if (j0 + 1 >= NTOK) { sacc[n].y = -1e30f; sacc[n].w = -1e30f; }
            }
        }
        float mA = -1e30f, mB = -1e30f;
        #pragma unroll
        for (int n = 0; n < 7; n++) {
            mA = fmaxf(mA, fmaxf(sacc[n].x, sacc[n].y));
            mB = fmaxf(mB, fmaxf(sacc[n].z, sacc[n].w));
        }
        #pragma unroll
        for (int o = 1; o <= 2; o <<= 1) {
            mA = fmaxf(mA, __shfl_xor_sync(~0u, mA, o));
            mB = fmaxf(mB, __shfl_xor_sync(~0u, mB, o));
        }
        float sA = 0.f, sB = 0.f;
        #pragma unroll
        for (int n = 0; n < 7; n++) {
            sacc[n].x = __expf(sacc[n].x - mA);
            sacc[n].y = __expf(sacc[n].y - mA);
            sacc[n].z = __expf(sacc[n].z - mB);
            sacc[n].w = __expf(sacc[n].w - mB);
            sA += sacc[n].x + sacc[n].y;
            sB += sacc[n].z + sacc[n].w;
        }
        #pragma unroll
        for (int o = 1; o <= 2; o <<= 1) {
            sA += __shfl_xor_sync(~0u, sA, o);
            sB += __shfl_xor_sync(~0u, sB, o);
        }
        float iA = 1.0f / sA, iB = 1.0f / sB;

        uint32_t pA[7], pB[7];
        #pragma unroll
        for (int n = 0; n < 7; n++) {
            pA[n] = h2u(sacc[n].x * iA, sacc[n].y * iA);
            pB[n] = h2u(sacc[n].z * iB, sacc[n].w * iB);
        }

        // attn @ V: B-frags via ldmatrix.trans on plain-layout V
        const int li  = lane & 7;
        const int grp = lane >> 3;
        float4 vacc[4];
        #pragma unroll
        for (int n = 0; n < 4; n++) vacc[n] = make_float4(0.f, 0.f, 0.f, 0.f);
        const uint32_t vB = smem_u32 + (uint32_t)
            (base + OFF_V + (((grp & 1) << 3) + li) * VS + h * 32 + ((grp >> 1) << 3)) * 2;
        #pragma unroll
        for (int kt = 0; kt < 4; kt++) {
            uint32_t addr = vB + (uint32_t)(kt * 16 * VS) * 2;
            uint32_t b00, b01, b10, b11;
            ldsm_x4_t(b00, b01, b10, b11, addr);
            uint32_t b20, b21, b30, b31;
            ldsm_x4_t(b20, b21, b30, b31, addr + 32);

            uint32_t a0 = pA[2 * kt], a1 = pB[2 * kt];
            uint32_t a2 = (2 * kt + 1 < 7) ? pA[2 * kt + 1] : 0u;  // j pad = 0
            uint32_t a3 = (2 * kt + 1 < 7) ? pB[2 * kt + 1] : 0u;
            mma16(vacc[0], a0, a1, a2, a3, b00, b01);
            mma16(vacc[1], a0, a1, a2, a3, b10, b11);
            mma16(vacc[2], a0, a1, a2, a3, b20, b21);
            mma16(vacc[3], a0, a1, a2, a3, b30, b31);
        }
        #pragma unroll
        for (int n = 0; n < 4; n++) {
            int c = h * 32 + n * 8 + 2 * tg;
            *(uint32_t*)&smh[base + OFF_X + r0 * SH + c]       = h2u(vacc[n].x, vacc[n].y);
            *(uint32_t*)&smh[base + OFF_X + (r0 + 8) * SH + c] = h2u(vacc[n].z, vacc[n].w);
        }
    }
    cp_wait<0>();        // g3 (proj weights) landed
    __syncthreads();     // B6: attn out + proj weights visible

    // ---- proj GEMM (buf1) -> global ----
    {
        float4 acc[2][2];
        #pragma unroll
        for (int n = 0; n < 2; n++) {
            float b0 = projb[n0 + n * 8 + 2 * tg];
            float b1 = projb[n0 + n * 8 + 2 * tg + 1];
            acc[0][n] = make_float4(b0, b1, b0, b1);
            acc[1][n] = acc[0][n];
        }
        #pragma unroll 4
        for (int kt = 0; kt < 8; kt++) {
            uint32_t koff = kt * 32u;
            uint32_t A0[4], A1[4], Bv[4];
            ldsm_x4(A0[0], A0[1], A0[2], A0[3], xA0 + koff);
            ldsm_x4(A1[0], A1[1], A1[2], A1[3], xA1 + koff);
            ldsm_x4(Bv[0], Bv[1], Bv[2], Bv[3], wB1 + koff);
            mma16(acc[0][0], A0[0], A0[1], A0[2], A0[3], Bv[0], Bv[1]);
            mma16(acc[0][1], A0[0], A0[1], A0[2], A0[3], Bv[2], Bv[3]);
            mma16(acc[1][0], A1[0], A1[1], A1[2], A1[3], Bv[0], Bv[1]);
            mma16(acc[1][1], A1[0], A1[1], A1[2], A1[3], Bv[2], Bv[3]);
        }

        #pragma unroll
        for (int m = 0; m < 2; m++) {
            #pragma unroll
            for (int rr = 0; rr < 2; rr++) {
                int r = (mb + m) * 16 + g + rr * 8;
                if (r < NTOK) {
                    #pragma unroll
                    for (int n = 0; n < 2; n++) {
                        float2 val = rr ? make_float2(acc[m][n].z, acc[m][n].w)
                                        : make_float2(acc[m][n].x, acc[m][n].y);
                        size_t o = (size_t)tokidx[wh * 64 + r] * 128 + n0 + n * 8 + 2 * tg;
                        if (BRANCH == 0) {
                            *(float2*)&out[o] = val;
                        } else {
                            asm volatile("red.global.add.v2.f32 [%0], {%1, %2};"
                                         :: "l"(out + o), "f"(val.x), "f"(val.y)
                                         : "memory");
                        }
                    }
                }
            }
        }
    }
}

// xy alone (plain stores must precede the REDG accumulators)
__global__ void __launch_bounds__(1024, 1)
win_xy_k(const float* __restrict__ x, const float* __restrict__ qkvb,
         const float* __restrict__ projb, float* __restrict__ out) {
    win_body<0, 49>(blockIdx.x, x, qkvb, projb, out);
}

// th + tw merged: both accumulate via REDG (commutative) -> one tail
__global__ void __launch_bounds__(1024, 1)
win_thw_k(const float* __restrict__ x,
          const float* __restrict__ qkvb1, const float* __restrict__ projb1,
          const float* __restrict__ qkvb2, const float* __restrict__ projb2,
          float* __restrict__ out) {
    int b = blockIdx.x;
    if (b < 1792) win_body<1, 56>(b, x, qkvb1, projb1, out);
    else          win_body<2, 56>(b - 1792, x, qkvb2, projb2, out);
}

extern "C" void kernel_launch(void* const* d_in, const int* in_sizes, int n_in,
                              void* d_out, int out_size)
{
    const float* x         = (const float*)d_in[0];
    const float* qkv_w     = (const float*)d_in[1];
    const float* qkv_b     = (const float*)d_in[2];
    const float* qkv_th_w  = (const float*)d_in[3];
    const float* qkv_th_b  = (const float*)d_in[4];
    const float* qkv_tw_w  = (const float*)d_in[5];
    const float* qkv_tw_b  = (const float*)d_in[6];
    const float* proj_w    = (const float*)d_in[7];
    const float* proj_b    = (const float*)d_in[8];
    const float* proj_th_w = (const float*)d_in[9];
    const float* proj_th_b = (const float*)d_in[10];
    const float* proj_tw_w = (const float*)d_in[11];
    const float* proj_tw_b = (const float*)d_in[12];
    float* out = (float*)d_out;

    conv_weights<<<768, 256>>>(qkv_w, qkv_th_w, qkv_tw_w,
                               proj_w, proj_th_w, proj_tw_w);

    cudaFuncSetAttribute(win_xy_k,
                         cudaFuncAttributeMaxDynamicSharedMemorySize, SMEM_BYTES);
    cudaFuncSetAttribute(win_thw_k,
                         cudaFuncAttributeMaxDynamicSharedMemorySize, SMEM_BYTES);

    // xy writes every output exactly once; th+tw accumulate concurrently.
    win_xy_k<<<2048, 1024, SMEM_BYTES>>>(x, qkv_b, proj_b, out);
    win_thw_k<<<3584, 1024, SMEM_BYTES>>>(x, qkv_th_b, proj_th_b,
                                          qkv_tw_b, proj_tw_b, out);
}

// round 14
// speedup vs baseline: 1.1643x; 1.0731x over previous
#include <cuda_runtime.h>
#include <cuda_fp16.h>
#include <cstdint>

// Problem constants: B=8, D=8, H=W=56, C=128, 4 heads x 32, windows (8,7,7),
// all pads zero. xy: 4096 windows x 49 tok; th/tw: 3584 x 56.
//
// 2 windows per CTA (1024 thr). ldmatrix everywhere on plain row-major smem
// (stride 136 halves -> conflict-free LDSM). P register-resident.
// R13: q+k computed in ONE pass (A-frags loaded once, W0=q / W1=k staged
// up-front); v+proj staged together behind the q+k pass; act-only syncs use
// per-half named barriers (bar.sync 1+wh, 512) so the two window-halves
// drift and hide each other's stalls. Full barriers: 3 (was 6).

static constexpr int SH   = 136;  // stride (halves) X/Q/K rows
static constexpr int WSH  = 136;  // stride staged weight rows
static constexpr int VS   = 136;  // stride V rows

static constexpr int OFF_X  = 0;                    // 64 x SH (x, later attn out)
static constexpr int OFF_Q  = OFF_X + 64 * SH;
static constexpr int OFF_K  = OFF_Q + 64 * SH;
static constexpr int OFF_V  = OFF_K + 64 * SH;
static constexpr int ACT_HALVES = OFF_V + 64 * VS;  // 34816
static constexpr int OFF_W0 = 2 * ACT_HALVES;       // weight buffer 0
static constexpr int OFF_W1 = OFF_W0 + 128 * WSH;   // weight buffer 1
static constexpr int TOT_HALVES = OFF_W1 + 128 * WSH;          // 104448
static constexpr int SMEM_BYTES = TOT_HALVES * 2 + 128 * 4;    // 209408 (1 CTA/SM)

// Pre-converted fp16 weights, PLAIN transposed: [n][k].
__device__ __align__(16) __half g_qkvwt[3][384 * 128];
__device__ __align__(16) __half g_projwt[3][128 * 128];

template <int BRANCH>
__device__ __forceinline__ int tok_index(int win, int tt) {
    if (BRANCH == 0) {                 // xy: (b, d, hb, wb) x (hh, ww)
        int b  = win >> 9;
        int d  = (win >> 6) & 7;
        int hb = (win >> 3) & 7;
        int wb = win & 7;
        int hh = tt / 7, wq = tt - hh * 7;
        return ((b * 8 + d) * 56 + hb * 7 + hh) * 56 + wb * 7 + wq;
    } else if (BRANCH == 1) {          // th: (b, hb, w) x (dd, hh)
        int b  = win / 448;
        int r  = win - b * 448;
        int hb = r / 56;
        int w  = r - hb * 56;
        int dd = tt / 7, hh = tt - dd * 7;
        return ((b * 8 + dd) * 56 + hb * 7 + hh) * 56 + w;
    } else {                           // tw: (b, h, wb) x (dd, ww)
        int b  = win / 448;
        int r  = win - b * 448;
        int h  = r >> 3;
        int wb = r & 7;
        int dd = tt / 7, wq = tt - dd * 7;
        return ((b * 8 + dd) * 56 + h) * 56 + wb * 7 + wq;
    }
}

__device__ __forceinline__ void mma16(float4& d, uint32_t a0, uint32_t a1,
                                      uint32_t a2, uint32_t a3,
                                      uint32_t b0, uint32_t b1) {
    asm volatile(
        "mma.sync.aligned.m16n8k16.row.col.f32.f16.f16.f32 "
        "{%0,%1,%2,%3}, {%4,%5,%6,%7}, {%8,%9}, {%0,%1,%2,%3};\n"
        : "+f"(d.x), "+f"(d.y), "+f"(d.z), "+f"(d.w)
        : "r"(a0), "r"(a1), "r"(a2), "r"(a3), "r"(b0), "r"(b1));
}

__device__ __forceinline__ void ldsm_x4(uint32_t& r0, uint32_t& r1,
                                        uint32_t& r2, uint32_t& r3, uint32_t addr) {
    asm volatile("ldmatrix.sync.aligned.m8n8.x4.shared.b16 {%0,%1,%2,%3}, [%4];"
                 : "=r"(r0), "=r"(r1), "=r"(r2), "=r"(r3) : "r"(addr));
}
__device__ __forceinline__ void ldsm_x2(uint32_t& r0, uint32_t& r1, uint32_t addr) {
    asm volatile("ldmatrix.sync.aligned.m8n8.x2.shared.b16 {%0,%1}, [%2];"
                 : "=r"(r0), "=r"(r1) : "r"(addr));
}
__device__ __forceinline__ void ldsm_x4_t(uint32_t& r0, uint32_t& r1,
                                          uint32_t& r2, uint32_t& r3, uint32_t addr) {
    asm volatile("ldmatrix.sync.aligned.m8n8.x4.trans.shared.b16 {%0,%1,%2,%3}, [%4];"
                 : "=r"(r0), "=r"(r1), "=r"(r2), "=r"(r3) : "r"(addr));
}

__device__ __forceinline__ void cp16(uint32_t dst, const void* src) {
    asm volatile("cp.async.cg.shared.global [%0], [%1], 16;" :: "r"(dst), "l"(src));
}
__device__ __forceinline__ void cp_commit() {
    asm volatile("cp.async.commit_group;" ::: "memory");
}
template <int N>
__device__ __forceinline__ void cp_wait() {
    asm volatile("cp.async.wait_group %0;" :: "n"(N) : "memory");
}
__device__ __forceinline__ void bar_half(int id) {
    asm volatile("bar.sync %0, 512;" :: "r"(id) : "memory");
}

__device__ __forceinline__ uint32_t h2u(float a, float b) {
    __half2 h = __floats2half2_rn(a, b);
    return *(uint32_t*)&h;
}

// ---------------- weight pre-conversion (plain transpose) ----------------
__global__ void conv_weights(const float* __restrict__ w0, const float* __restrict__ w1,
                             const float* __restrict__ w2, const float* __restrict__ p0,
                             const float* __restrict__ p1, const float* __restrict__ p2) {
    int tid = blockIdx.x * 256 + threadIdx.x;
    const int QK = 3 * 384 * 128;
    if (tid < QK) {
        int br  = tid / (384 * 128);
        int rem = tid - br * 384 * 128;
        int n = rem >> 7, k = rem & 127;
        const float* src = (br == 0) ? w0 : (br == 1 ? w1 : w2);
        g_qkvwt[br][rem] = __float2half_rn(src[k * 384 + n]);
    } else {
        int t2  = tid - QK;
        int br  = t2 / (128 * 128);
        int rem = t2 - br * 16384;
        int n = rem >> 7, k = rem & 127;
        const float* src = (br == 0) ? p0 : (br == 1 ? p1 : p2);
        g_projwt[br][rem] = __float2half_rn(src[k * 128 + n]);
    }
}

// ------------- fused window attention body, TWO windows per CTA -------------
template <int BRANCH, int NTOK>
__device__ __forceinline__ void
win_body(int cta, const float* __restrict__ x,
         const float* __restrict__ qkvb, const float* __restrict__ projb,
         float* __restrict__ out)
{
    extern __shared__ __align__(16) __half smh[];
    int* tokidx = (int*)(smh + TOT_HALVES);
    const uint32_t smem_u32 = (uint32_t)__cvta_generic_to_shared(smh);

    const int t    = threadIdx.x;          // 0..1023
    const int wh   = t >> 9;               // window half 0/1
    const int tl   = t & 511;
    const int lane = t & 31;
    const int wrp  = tl >> 5;              // local warp 0..15
    const int g    = lane >> 2;
    const int tg   = lane & 3;
    const int win  = cta * 2 + wh;
    const int base = wh * ACT_HALVES;

    const int aRow = lane & 15;
    const int aCol = (lane >> 4) << 3;
    const int bRow = (lane & 7) + ((lane >> 4) << 3);
    const int bCol = ((lane >> 3) & 1) << 3;

    // ---- stage q->W0 (g0), k->W1 (g1) BEFORE x-load ----
    {
        const __half* wq = g_qkvwt[BRANCH];
        const __half* wk = g_qkvwt[BRANCH] + 128 * 128;
        for (int idx = t; idx < 128 * 16; idx += 1024) {
            int rw = idx >> 4, c8 = idx & 15;
            cp16(smem_u32 + (uint32_t)(OFF_W0 + rw * WSH + c8 * 8) * 2,
                 wq + rw * 128 + c8 * 8);
            cp16(smem_u32 + (uint32_t)(OFF_W1 + rw * WSH + c8 * 8) * 2,
                 wk + rw * 128 + c8 * 8);
        }
        cp_commit();
    }

    if (tl < NTOK) tokidx[wh * 64 + tl] = tok_index<BRANCH>(win, tl);

    // ---- x -> X (fp16, plain rows), pad rows zeroed ----
    for (int idx = tl; idx < 64 * 32; idx += 512) {
        int r = idx >> 5, q = idx & 31;
        uint2 u = make_uint2(0u, 0u);
        if (r < NTOK) {
            float4 v = *(const float4*)
                (x + (size_t)tok_index<BRANCH>(win, r) * 128 + q * 4);
            u.x = h2u(v.x, v.y);
            u.y = h2u(v.z, v.w);
        }
        *(uint2*)&smh[base + OFF_X + r * SH + q * 4] = u;
    }

    const int mb = (wrp & 1) * 2;        // m-tiles {mb, mb+1}
    const int n0 = (wrp >> 1) * 16;      // n columns [n0, n0+16)
    const float qscale = 0.1767766952966369f;

    const uint32_t xA0 = smem_u32 +
        (uint32_t)(base + OFF_X + (mb * 16 + aRow) * SH + aCol) * 2;
    const uint32_t xA1 = xA0 + 16u * SH * 2u;
    const uint32_t wB0 = smem_u32 + (uint32_t)(OFF_W0 + (n0 + bRow) * WSH + bCol) * 2;
    const uint32_t wB1 = smem_u32 + (uint32_t)(OFF_W1 + (n0 + bRow) * WSH + bCol) * 2;

    // ---- q + k in ONE pass (A loaded once, B from W0 and W1) ----
    cp_wait<0>();
    __syncthreads();     // B1: x + q/k weights visible
    {
        float4 accq[2][2], acck[2][2];
        #pragma unroll
        for (int n = 0; n < 2; n++) {
            float q0 = qkvb[n0 + n * 8 + 2 * tg];
            float q1 = qkvb[n0 + n * 8 + 2 * tg + 1];
            float k0 = qkvb[128 + n0 + n * 8 + 2 * tg];
            float k1 = qkvb[128 + n0 + n * 8 + 2 * tg + 1];
            accq[0][n] = make_float4(q0, q1, q0, q1);
            accq[1][n] = accq[0][n];
            acck[0][n] = make_float4(k0, k1, k0, k1);
            acck[1][n] = acck[0][n];
        }
        #pragma unroll 2
        for (int kt = 0; kt < 8; kt++) {
            uint32_t koff = kt * 32u;
            uint32_t A0[4], A1[4], Bq[4], Bk[4];
            ldsm_x4(A0[0], A0[1], A0[2], A0[3], xA0 + koff);
            ldsm_x4(A1[0], A1[1], A1[2], A1[3], xA1 + koff);
            ldsm_x4(Bq[0], Bq[1], Bq[2], Bq[3], wB0 + koff);
            ldsm_x4(Bk[0], Bk[1], Bk[2], Bk[3], wB1 + koff);
            mma16(accq[0][0], A0[0], A0[1], A0[2], A0[3], Bq[0], Bq[1]);
            mma16(accq[0][1], A0[0], A0[1], A0[2], A0[3], Bq[2], Bq[3]);
            mma16(accq[1][0], A1[0], A1[1], A1[2], A1[3], Bq[0], Bq[1]);
            mma16(accq[1][1], A1[0], A1[1], A1[2], A1[3], Bq[2], Bq[3]);
            mma16(acck[0][0], A0[0], A0[1], A0[2], A0[3], Bk[0], Bk[1]);
            mma16(acck[0][1], A0[0], A0[1], A0[2], A0[3], Bk[2], Bk[3]);
            mma16(acck[1][0], A1[0], A1[1], A1[2], A1[3], Bk[0], Bk[1]);
            mma16(acck[1][1], A1[0], A1[1], A1[2], A1[3], Bk[2], Bk[3]);
        }
        #pragma unroll
        for (int m = 0; m < 2; m++) {
            int r = (mb + m) * 16 + g;
            #pragma unroll
            for (int n = 0; n < 2; n++) {
                int c = n0 + n * 8 + 2 * tg;
                *(uint32_t*)&smh[base + OFF_Q + r * SH + c] =
                    h2u(accq[m][n].x * qscale, accq[m][n].y * qscale);
                *(uint32_t*)&smh[base + OFF_Q + (r + 8) * SH + c] =
                    h2u(accq[m][n].z * qscale, accq[m][n].w * qscale);
                *(uint32_t*)&smh[base + OFF_K + r * SH + c] =
                    h2u(acck[m][n].x, acck[m][n].y);
                *(uint32_t*)&smh[base + OFF_K + (r + 8) * SH + c] =
                    h2u(acck[m][n].z, acck[m][n].w);
            }
        }
    }
    __syncthreads();     // B2: W0+W1 free for restage

    // ---- restage v->W0, proj->W1 together ----
    {
        const __half* wv = g_qkvwt[BRANCH] + 2 * 128 * 128;
        const __half* pw = g_projwt[BRANCH];
        for (int idx = t; idx < 128 * 16; idx += 1024) {
            int rw = idx >> 4, c8 = idx & 15;
            cp16(smem_u32 + (uint32_t)(OFF_W0 + rw * WSH + c8 * 8) * 2,
                 wv + rw * 128 + c8 * 8);
            cp16(smem_u32 + (uint32_t)(OFF_W1 + rw * WSH + c8 * 8) * 2,
                 pw + rw * 128 + c8 * 8);
        }
        cp_commit();
    }
    cp_wait<0>();
    __syncthreads();     // B3: v + proj weights visible (last full barrier)

    // ---- v chunk (W0) ----
    {
        float4 acc[2][2];
        #pragma unroll
        for (int n = 0; n < 2; n++) {
            float b0 = qkvb[256 + n0 + n * 8 + 2 * tg];
            float b1 = qkvb[256 + n0 + n * 8 + 2 * tg + 1];
            acc[0][n] = make_float4(b0, b1, b0, b1);
            acc[1][n] = acc[0][n];
        }
        #pragma unroll 4
        for (int kt = 0; kt < 8; kt++) {
            uint32_t koff = kt * 32u;
            uint32_t A0[4], A1[4], Bv[4];
            ldsm_x4(A0[0], A0[1], A0[2], A0[3], xA0 + koff);
            ldsm_x4(A1[0], A1[1], A1[2], A1[3], xA1 + koff);
            ldsm_x4(Bv[0], Bv[1], Bv[2], Bv[3], wB0 + koff);
            mma16(acc[0][0], A0[0], A0[1], A0[2], A0[3], Bv[0], Bv[1]);
            mma16(acc[0][1], A0[0], A0[1], A0[2], A0[3], Bv[2], Bv[3]);
            mma16(acc[1][0], A1[0], A1[1], A1[2], A1[3], Bv[0], Bv[1]);
            mma16(acc[1][1], A1[0], A1[1], A1[2], A1[3], Bv[2], Bv[3]);
        }
        #pragma unroll
        for (int m = 0; m < 2; m++) {
            int r = (mb + m) * 16 + g;
            #pragma unroll
            for (int n = 0; n < 2; n++) {
                int c = n0 + n * 8 + 2 * tg;
                *(uint32_t*)&smh[base + OFF_V + r * VS + c] =
                    h2u(acc[m][n].x, acc[m][n].y);
                *(uint32_t*)&smh[base + OFF_V + (r + 8) * VS + c] =
                    h2u(acc[m][n].z, acc[m][n].w);
            }
        }
    }
    bar_half(1 + wh);    // B4 (per-half): Q, K, V visible to this half

    // ---- scores + softmax + P@V, P fully register-resident ----
    const int h  = wrp >> 2;
    const int mt = wrp & 3;
    const int r0 = mt * 16 + g;
    {
        const uint32_t qA = smem_u32 +
            (uint32_t)(base + OFF_Q + (mt * 16 + aRow) * SH + h * 32 + aCol) * 2;
        uint32_t kB[3];
        #pragma unroll
        for (int nn = 0; nn < 3; nn++)
            kB[nn] = smem_u32 +
                (uint32_t)(base + OFF_K + (nn * 16 + bRow) * SH + h * 32 + bCol) * 2;
        const uint32_t kB2 = smem_u32 +
            (uint32_t)(base + OFF_K + (48 + (lane & 7)) * SH + h * 32 + bCol) * 2;

        float4 sacc[7];
        #pragma unroll
        for (int n = 0; n < 7; n++) sacc[n] = make_float4(0.f, 0.f, 0.f, 0.f);
        #pragma unroll
        for (int kt = 0; kt < 2; kt++) {
            uint32_t koff = kt * 32u;
            uint32_t Aq[4];
            ldsm_x4(Aq[0], Aq[1], Aq[2], Aq[3], qA + koff);
            #pragma unroll
            for (int nn = 0; nn < 3; nn++) {
                uint32_t Bk[4];
                ldsm_x4(Bk[0], Bk[1], Bk[2], Bk[3], kB[nn] + koff);
                mma16(sacc[2 * nn],     Aq[0], Aq[1], Aq[2], Aq[3], Bk[0], Bk[1]);
                mma16(sacc[2 * nn + 1], Aq[0], Aq[1], Aq[2], Aq[3], Bk[2], Bk[3]);
            }
            uint32_t b0, b1;
            ldsm_x2(b0, b1, kB2 + koff);
            mma16(sacc[6], Aq[0], Aq[1], Aq[2], Aq[3], b0, b1);
        }

        if (NTOK < 56) {
            #pragma unroll
            for (int n = 0; n < 7; n++) {
                int j0 = 8 * n + 2 * tg;
                if (j0 >= NTOK)     { sacc[n].x = -1e30f; sacc[n].z = -1e30f; }
                if (j0 + 1 >= NTOK) { sacc[n].y = -1e30f; sacc[n].w = -1e30f; }
            }
        }
        float mA = -1e30f, mB = -1e30f;
        #pragma unroll
        for (int n = 0; n < 7; n++) {
            mA = fmaxf(mA, fmaxf(sacc[n].x, sacc[n].y));
            mB = fmaxf(mB, fmaxf(sacc[n].z, sacc[n].w));
        }
        #pragma unroll
        for (int o = 1; o <= 2; o <<= 1) {
            mA = fmaxf(mA, __shfl_xor_sync(~0u, mA, o));
            mB = fmaxf(mB, __shfl_xor_sync(~0u, mB, o));
        }
        float sA = 0.f, sB = 0.f;
        #pragma unroll
        for (int n = 0; n < 7; n++) {
            sacc[n].x = __expf(sacc[n].x - mA);
            sacc[n].y = __expf(sacc[n].y - mA);
            sacc[n].z = __expf(sacc[n].z - mB);
            sacc[n].w = __expf(sacc[n].w - mB);
            sA += sacc[n].x + sacc[n].y;
            sB += sacc[n].z + sacc[n].w;
        }
        #pragma unroll
        for (int o = 1; o <= 2; o <<= 1) {
            sA += __shfl_xor_sync(~0u, sA, o);
            sB += __shfl_xor_sync(~0u, sB, o);
        }
        float iA = 1.0f / sA, iB = 1.0f / sB;

        uint32_t pA[7], pB[7];
        #pragma unroll
        for (int n = 0; n < 7; n++) {
            pA[n] = h2u(sacc[n].x * iA, sacc[n].y * iA);
            pB[n] = h2u(sacc[n].z * iB, sacc[n].w * iB);
        }

        // attn @ V: B-frags via ldmatrix.trans on plain-layout V
        const int li  = lane & 7;
        const int grp = lane >> 3;
        float4 vacc[4];
        #pragma unroll
        for (int n = 0; n < 4; n++) vacc[n] = make_float4(0.f, 0.f, 0.f, 0.f);
        const uint32_t vB = smem_u32 + (uint32_t)
            (base + OFF_V + (((grp & 1) << 3) + li) * VS + h * 32 + ((grp >> 1) << 3)) * 2;
        #pragma unroll
        for (int kt = 0; kt < 4; kt++) {
            uint32_t addr = vB + (uint32_t)(kt * 16 * VS) * 2;
            uint32_t b00, b01, b10, b11;
            ldsm_x4_t(b00, b01, b10, b11, addr);
            uint32_t b20, b21, b30, b31;
            ldsm_x4_t(b20, b21, b30, b31, addr + 32);

            uint32_t a0 = pA[2 * kt], a1 = pB[2 * kt];
            uint32_t a2 = (2 * kt + 1 < 7) ? pA[2 * kt + 1] : 0u;  // j pad = 0
            uint32_t a3 = (2 * kt + 1 < 7) ? pB[2 * kt + 1] : 0u;
            mma16(vacc[0], a0, a1, a2, a3, b00, b01);
            mma16(vacc[1], a0, a1, a2, a3, b10, b11);
            mma16(vacc[2], a0, a1, a2, a3, b20, b21);
            mma16(vacc[3], a0, a1, a2, a3, b30, b31);
        }
        #pragma unroll
        for (int n = 0; n < 4; n++) {
            int c = h * 32 + n * 8 + 2 * tg;
            *(uint32_t*)&smh[base + OFF_X + r0 * SH + c]       = h2u(vacc[n].x, vacc[n].y);
            *(uint32_t*)&smh[base + OFF_X + (r0 + 8) * SH + c] = h2u(vacc[n].z, vacc[n].w);
        }
    }
    bar_half(1 + wh);    // B5 (per-half): attn output visible to this half

    // ---- proj GEMM (W1) -> global ----
    {
        float4 acc[2][2];
        #pragma unroll
        for (int n = 0; n < 2; n++) {
            float b0 = projb[n0 + n * 8 + 2 * tg];
            float b1 = projb[n0 + n * 8 + 2 * tg + 1];
            acc[0][n] = make_float4(b0, b1, b0, b1);
            acc[1][n] = acc[0][n];
        }
        #pragma unroll 4
        for (int kt = 0; kt < 8; kt++) {
            uint32_t koff = kt * 32u;
            uint32_t A0[4], A1[4], Bv[4];
            ldsm_x4(A0[0], A0[1], A0[2], A0[3], xA0 + koff);
            ldsm_x4(A1[0], A1[1], A1[2], A1[3], xA1 + koff);
            ldsm_x4(Bv[0], Bv[1], Bv[2], Bv[3], wB1 + koff);
            mma16(acc[0][0], A0[0], A0[1], A0[2], A0[3], Bv[0], Bv[1]);
            mma16(acc[0][1], A0[0], A0[1], A0[2], A0[3], Bv[2], Bv[3]);
            mma16(acc[1][0], A1[0], A1[1], A1[2], A1[3], Bv[0], Bv[1]);
            mma16(acc[1][1], A1[0], A1[1], A1[2], A1[3], Bv[2], Bv[3]);
        }

        #pragma unroll
        for (int m = 0; m < 2; m++) {
            #pragma unroll
            for (int rr = 0; rr < 2; rr++) {
                int r = (mb + m) * 16 + g + rr * 8;
                if (r < NTOK) {
                    #pragma unroll
                    for (int n = 0; n < 2; n++) {
                        float2 val = rr ? make_float2(acc[m][n].z, acc[m][n].w)
                                        : make_float2(acc[m][n].x, acc[m][n].y);
                        size_t o = (size_t)tokidx[wh * 64 + r] * 128 + n0 + n * 8 + 2 * tg;
                        if (BRANCH == 0) {
                            *(float2*)&out[o] = val;
                        } else {
                            asm volatile("red.global.add.v2.f32 [%0], {%1, %2};"
                                         :: "l"(out + o), "f"(val.x), "f"(val.y)
                                         : "memory");
                        }
                    }
                }
            }
        }
    }
}

// xy alone (plain stores must precede the REDG accumulators)
__global__ void __launch_bounds__(1024, 1)
win_xy_k(const float* __restrict__ x, const float* __restrict__ qkvb,
         const float* __restrict__ projb, float* __restrict__ out) {
    win_body<0, 49>(blockIdx.x, x, qkvb, projb, out);
}

// th + tw merged: both accumulate via REDG (commutative) -> one tail
__global__ void __launch_bounds__(1024, 1)
win_thw_k(const float* __restrict__ x,
          const float* __restrict__ qkvb1, const float* __restrict__ projb1,
          const float* __restrict__ qkvb2, const float* __restrict__ projb2,
          float* __restrict__ out) {
    int b = blockIdx.x;
    if (b < 1792) win_body<1, 56>(b, x, qkvb1, projb1, out);
    else          win_body<2, 56>(b - 1792, x, qkvb2, projb2, out);
}

extern "C" void kernel_launch(void* const* d_in, const int* in_sizes, int n_in,
                              void* d_out, int out_size)
{
    const float* x         = (const float*)d_in[0];
    const float* qkv_w     = (const float*)d_in[1];
    const float* qkv_b     = (const float*)d_in[2];
    const float* qkv_th_w  = (const float*)d_in[3];
    const float* qkv_th_b  = (const float*)d_in[4];
    const float* qkv_tw_w  = (const float*)d_in[5];
    const float* qkv_tw_b  = (const float*)d_in[6];
    const float* proj_w    = (const float*)d_in[7];
    const float* proj_b    = (const float*)d_in[8];
    const float* proj_th_w = (const float*)d_in[9];
    const float* proj_th_b = (const float*)d_in[10];
    const float* proj_tw_w = (const float*)d_in[11];
    const float* proj_tw_b = (const float*)d_in[12];
    float* out = (float*)d_out;

    conv_weights<<<768, 256>>>(qkv_w, qkv_th_w, qkv_tw_w,
                               proj_w, proj_th_w, proj_tw_w);

    cudaFuncSetAttribute(win_xy_k,
                         cudaFuncAttributeMaxDynamicSharedMemorySize, SMEM_BYTES);
    cudaFuncSetAttribute(win_thw_k,
                         cudaFuncAttributeMaxDynamicSharedMemorySize, SMEM_BYTES);

    // xy writes every output exactly once; th+tw accumulate concurrently.
    win_xy_k<<<2048, 1024, SMEM_BYTES>>>(x, qkv_b, proj_b, out);
    win_thw_k<<<3584, 1024, SMEM_BYTES>>>(x, qkv_th_b, proj_th_b,
                                          qkv_tw_b, proj_tw_b, out);
}